// round 14
// baseline (speedup 1.0000x reference)
#include <cuda_runtime.h>
#include <cuda_fp16.h>
#include <cuda_bf16.h>
#include <math.h>

// ---------------- problem constants ----------------
#define NN    12032
#define DMODEL 512
#define BGR   16
#define SEQ   256
#define NH    8
#define DH    64
#define LMAX  992
#define LATD  768
#define ROWS_Q  (BGR*LMAX)   // 15872
#define ROWS_KV (BGR*SEQ)    // 4096

// ---------------- scratch ----------
__device__ __half g_dense_h[ROWS_Q*DMODEL];
__device__ __half g_qh2 [ROWS_Q*DMODEL];
__device__ __half g_kh2 [ROWS_KV*DMODEL];
__device__ __half g_vh2 [ROWS_KV*DMODEL];
__device__ __half g_ctx [ROWS_Q*DMODEL];
__device__ float  g_y   [ROWS_Q*DMODEL];
__device__ __half g_x1h [ROWS_Q*DMODEL];
__device__ float  g_h   [ROWS_Q*DMODEL];
__device__ __half g_WqT [DMODEL*DMODEL];
__device__ __half g_WkT [LATD*DMODEL];
__device__ __half g_WvT [LATD*DMODEL];
__device__ __half g_WoT [DMODEL*DMODEL];
__device__ __half g_W1T [DMODEL*DMODEL];
__device__ __half g_cond[BGR*SEQ*LATD];
__device__ __half g_Wqh [DMODEL*DMODEL];
__device__ __half g_Wkh [LATD*DMODEL];
__device__ __half g_Wvh [LATD*DMODEL];
__device__ __half g_inwT[3*DMODEL*DMODEL];
__device__ float  g_bq2 [DMODEL];
__device__ float  g_bk2 [DMODEL];
__device__ float  g_bv2 [DMODEL];

// ---------------- helpers ----------------
__device__ __forceinline__ void mma_f16(float c[4],
    unsigned a0, unsigned a1, unsigned a2, unsigned a3,
    unsigned b0, unsigned b1)
{
    asm volatile(
        "mma.sync.aligned.m16n8k16.row.col.f32.f16.f16.f32 "
        "{%0,%1,%2,%3}, {%4,%5,%6,%7}, {%8,%9}, {%0,%1,%2,%3};"
        : "+f"(c[0]), "+f"(c[1]), "+f"(c[2]), "+f"(c[3])
        : "r"(a0), "r"(a1), "r"(a2), "r"(a3), "r"(b0), "r"(b1));
}

#define CP16(dst, src) asm volatile("cp.async.cg.shared.global [%0], [%1], 16;" :: "r"(dst), "l"(src))
#define LDSM4(r, addr) asm volatile( \
    "ldmatrix.sync.aligned.m8n8.x4.shared.b16 {%0,%1,%2,%3}, [%4];" \
    : "=r"((r)[0]), "=r"((r)[1]), "=r"((r)[2]), "=r"((r)[3]) : "r"(addr))
#define LDSM2T(r, addr) asm volatile( \
    "ldmatrix.sync.aligned.m8n8.x2.trans.shared.b16 {%0,%1}, [%2];" \
    : "=r"((r)[0]), "=r"((r)[1]) : "r"(addr))

__device__ __forceinline__ int lower_bound_gb(const int* __restrict__ gb, int b) {
    int lo = 0, hi = NN;
    while (lo < hi) { int mid = (lo + hi) >> 1; if (gb[mid] < b) lo = mid + 1; else hi = mid; }
    return lo;
}

// ---------------- mega-prologue ----------
#define PM_PAD   ROWS_Q             // 15872
#define PM_COND  (PM_PAD + 2048)    // 17920
#define PM_HT    (PM_COND + 512)    // 18432
#define PM_BIAS  (PM_HT + 48)       // 18480
#define PM_CONVW (PM_BIAS + 512)    // 18992
#define PM_TINW  (PM_CONVW + 768)   // 19760 (grid size)

__global__ __launch_bounds__(128) void prologue_misc(
    const float* __restrict__ nodes, const int* __restrict__ gb,
    const float* __restrict__ cond,  const float* __restrict__ Wo,
    const float* __restrict__ W1,
    const float* __restrict__ Wq, const float* __restrict__ Wk,
    const float* __restrict__ Wv,
    const float* __restrict__ bq, const float* __restrict__ bk,
    const float* __restrict__ bv, const float* __restrict__ inw,
    const float* __restrict__ inb,
    __half* __restrict__ dense_h,
    __half* __restrict__ cond_h, __half* __restrict__ WoT, __half* __restrict__ W1T,
    __half* __restrict__ Wqh, __half* __restrict__ Wkh, __half* __restrict__ Wvh,
    __half* __restrict__ inwT,
    float* __restrict__ bq2, float* __restrict__ bk2, float* __restrict__ bv2)
{
    __shared__ float sh[32*33];
    int bid = blockIdx.x, tid = threadIdx.x;
    if (bid < PM_PAD) {
        int r = bid;
        int b = r / LMAX, pp = r - b*LMAX;
        int start = lower_bound_gb(gb, b);
        int i = start + pp;
        float4 v = make_float4(0.f, 0.f, 0.f, 0.f);
        if (i < NN && gb[i] == b)
            v = ((const float4*)(nodes + (size_t)i*DMODEL))[tid];
        __half2* dh = (__half2*)(dense_h + (size_t)r*DMODEL);
        dh[tid*2]   = __floats2half2_rn(v.x, v.y);
        dh[tid*2+1] = __floats2half2_rn(v.z, v.w);
    } else if (bid < PM_COND) {
        int j = bid - PM_PAD;
        int n4 = (BGR*SEQ*LATD) >> 2;
        for (int i = j*128 + tid; i < n4; i += 2048*128) {
            float4 v = ((const float4*)cond)[i];
            __half2* d = (__half2*)cond_h;
            d[i*2]   = __floats2half2_rn(v.x, v.y);
            d[i*2+1] = __floats2half2_rn(v.z, v.w);
        }
    } else if (bid < PM_HT) {
        int t = bid - PM_COND;
        int z = t >> 8, rem = t & 255;
        const float* s = z ? W1 : Wo;
        __half* d = z ? W1T : WoT;
        int bx = (rem & 15)*32, by = (rem >> 4)*32;
        int x = tid & 31, y0 = tid >> 5;
        #pragma unroll
        for (int i = 0; i < 32; i += 4)
            sh[(y0+i)*33 + x] = s[(size_t)(by + y0 + i)*DMODEL + bx + x];
        __syncthreads();
        #pragma unroll
        for (int i = 0; i < 32; i += 4)
            d[(size_t)(bx + y0 + i)*DMODEL + by + x] = __float2half_rn(sh[x*33 + y0+i]);
    } else if (bid < PM_BIAS) {
        int t = bid - PM_HT;
        int z = t >> 4, blk = t & 15;
        const float* bin = (z==0) ? bq : (z==1) ? bk : bv;
        const float* W = inw + (size_t)z*DMODEL*DMODEL;
        const float* ab = inb + z*DMODEL;
        float* outp = (z==0) ? bq2 : (z==1) ? bk2 : bv2;
        int jj = tid & 31;
        int r = tid >> 5;
        int j = blk*32 + jj;
        float a = 0.f;
        #pragma unroll 8
        for (int i = r*128; i < r*128 + 128; i++)
            a += bin[i]*W[(size_t)i*DMODEL + j];
        sh[r*32 + jj] = a;
        __syncthreads();
        if (r == 0) {
            float s = ab[j];
            #pragma unroll
            for (int k = 0; k < 4; k++) s += sh[k*32 + jj];
            outp[j] = s;
        }
    } else if (bid < PM_CONVW) {
        int t = bid - PM_BIAS;
        #pragma unroll
        for (int i = 0; i < 4; i++) {
            int idx = t*512 + i*128 + tid;
            const float* src; __half* dst; int loc;
            if (idx < 65536)       { src = Wq; dst = Wqh; loc = idx; }
            else if (idx < 163840) { src = Wk; dst = Wkh; loc = idx - 65536; }
            else                   { src = Wv; dst = Wvh; loc = idx - 163840; }
            float4 v = ((const float4*)src)[loc];
            ((__half2*)dst)[loc*2]   = __floats2half2_rn(v.x, v.y);
            ((__half2*)dst)[loc*2+1] = __floats2half2_rn(v.z, v.w);
        }
    } else {
        int t = bid - PM_CONVW;
        int z = t >> 8, rem = t & 255;
        const float* s = inw + (size_t)z*DMODEL*DMODEL;
        __half* d = inwT + (size_t)z*DMODEL*DMODEL;
        int bx = (rem & 15)*32, by = (rem >> 4)*32;
        int x = tid & 31, y0 = tid >> 5;
        #pragma unroll
        for (int i = 0; i < 32; i += 4)
            sh[(y0+i)*33 + x] = s[(size_t)(by + y0 + i)*DMODEL + bx + x];
        __syncthreads();
        #pragma unroll
        for (int i = 0; i < 32; i += 4)
            d[(size_t)(bx + y0 + i)*DMODEL + by + x] = __float2half_rn(sh[x*33 + y0+i]);
    }
}

// ---------------- 3-stage cp.async FP16 GEMM ----------------
#define TSTRH 40
#define STG_B (128*TSTRH*2)
#define GEMM_SMEM (3*2*STG_B)

template<int MODE>
__device__ __forceinline__ void gemm_body(
    const __half* __restrict__ A, const __half* __restrict__ Bt,
    const float* __restrict__ bias, const __half* __restrict__ DmH,
    void* __restrict__ Cv, int N, int K, char* smem, int Mstr, int by)
{
    char* As = smem;
    char* Bs = smem + 3*STG_B;

    int tid = threadIdx.x;
    int warp = tid >> 5, lane = tid & 31;
    int warp_m = warp & 3, warp_n = warp >> 2;
    int p = lane >> 2, q = lane & 3;
    int blockM = by * 128;
    int blockN = blockIdx.x * 128;

    int c0 = tid*2, c1 = c0 + 1;
    int r0c = c0 >> 2, k0c = (c0 & 3)*8;
    int r1c = c1 >> 2, k1c = (c1 & 3)*8;

    const __half* gA0 = A  + (size_t)(blockM + r0c)*K + k0c;
    const __half* gA1 = A  + (size_t)(blockM + r1c)*K + k1c;
    const __half* gB0 = Bt + (size_t)(blockN + r0c)*K + k0c;
    const __half* gB1 = Bt + (size_t)(blockN + r1c)*K + k1c;

    unsigned sa = (unsigned)__cvta_generic_to_shared(As);
    unsigned sb = (unsigned)__cvta_generic_to_shared(Bs);
    unsigned dA0[3], dA1[3], dB0[3], dB1[3];
    #pragma unroll
    for (int s = 0; s < 3; s++) {
        dA0[s] = sa + s*STG_B + (r0c*TSTRH + k0c)*2;
        dA1[s] = sa + s*STG_B + (r1c*TSTRH + k1c)*2;
        dB0[s] = sb + s*STG_B + (r0c*TSTRH + k0c)*2;
        dB1[s] = sb + s*STG_B + (r1c*TSTRH + k1c)*2;
    }

    unsigned aBase = sa + ((warp_m*32 + (lane & 15))*TSTRH + (lane >> 4)*8)*2;
    unsigned bBase = sb + ((warp_n*64 + ((lane >> 4) << 3) + (lane & 7))*TSTRH
                           + ((lane >> 3) & 1)*8)*2;

    float acc[2][8][4];
    #pragma unroll
    for (int mt = 0; mt < 2; mt++)
        #pragma unroll
        for (int nt = 0; nt < 8; nt++)
            #pragma unroll
            for (int i = 0; i < 4; i++) acc[mt][nt][i] = 0.f;

    CP16(dA0[0], gA0); CP16(dA1[0], gA1);
    CP16(dB0[0], gB0); CP16(dB1[0], gB1);
    asm volatile("cp.async.commit_group;");
    CP16(dA0[1], gA0 + 32); CP16(dA1[1], gA1 + 32);
    CP16(dB0[1], gB0 + 32); CP16(dB1[1], gB1 + 32);
    asm volatile("cp.async.commit_group;");

    int nk = K >> 5;
    int sc = 0, sp = 2;
    for (int t = 0; t < nk; t++) {
        asm volatile("cp.async.wait_group 1;");
        __syncthreads();
        if (t + 2 < nk) {
            int kt = (t + 2) << 5;
            CP16(dA0[sp], gA0 + kt); CP16(dA1[sp], gA1 + kt);
            CP16(dB0[sp], gB0 + kt); CP16(dB1[sp], gB1 + kt);
        }
        asm volatile("cp.async.commit_group;");
        unsigned ao = aBase + sc*STG_B;
        unsigned bo = bBase + sc*STG_B;
        #pragma unroll
        for (int kk = 0; kk < 32; kk += 16) {
            unsigned afr[2][4];
            LDSM4(afr[0], ao + kk*2);
            LDSM4(afr[1], ao + (16*TSTRH + kk)*2);
            unsigned bfr[4][4];
            #pragma unroll
            for (int j = 0; j < 4; j++)
                LDSM4(bfr[j], bo + (j*16*TSTRH + kk)*2);
            #pragma unroll
            for (int mt = 0; mt < 2; mt++)
                #pragma unroll
                for (int nt = 0; nt < 8; nt++)
                    mma_f16(acc[mt][nt],
                            afr[mt][0], afr[mt][1], afr[mt][2], afr[mt][3],
                            bfr[nt >> 1][(nt & 1)*2], bfr[nt >> 1][(nt & 1)*2 + 1]);
        }
        sc++; if (sc == 3) sc = 0;
        sp++; if (sp == 3) sp = 0;
    }

    #pragma unroll
    for (int mt = 0; mt < 2; mt++) {
        int r0 = blockM + warp_m*32 + mt*16 + p;
        #pragma unroll
        for (int nt = 0; nt < 8; nt++) {
            int c0c = blockN + warp_n*64 + nt*8 + 2*q;
            float b0 = 0.f, b1 = 0.f;
            if (bias) { b0 = bias[c0c]; b1 = bias[c0c+1]; }
            float v0 = acc[mt][nt][0] + b0;
            float v1 = acc[mt][nt][1] + b1;
            float v2 = acc[mt][nt][2] + b0;
            float v3 = acc[mt][nt][3] + b1;
            if (MODE == 4) {
                __half* Ch = (__half*)Cv;
                Ch[(size_t)(c0c  )*Mstr + r0    ] = __float2half_rn(v0);
                Ch[(size_t)(c0c+1)*Mstr + r0    ] = __float2half_rn(v1);
                Ch[(size_t)(c0c  )*Mstr + r0 + 8] = __float2half_rn(v2);
                Ch[(size_t)(c0c+1)*Mstr + r0 + 8] = __float2half_rn(v3);
            } else {
                size_t o0 = (size_t)r0*N + c0c;
                size_t o1 = (size_t)(r0+8)*N + c0c;
                if (MODE == 3) {
                    __half* Ch = (__half*)Cv;
                    *(__half2*)&Ch[o0] = __floats2half2_rn(v0, v1);
                    *(__half2*)&Ch[o1] = __floats2half2_rn(v2, v3);
                } else {
                    float* C = (float*)Cv;
                    if (MODE == 2) {
                        v0 = (v0 > 0.f) ? v0 : 0.01f*v0;
                        v1 = (v1 > 0.f) ? v1 : 0.01f*v1;
                        v2 = (v2 > 0.f) ? v2 : 0.01f*v2;
                        v3 = (v3 > 0.f) ? v3 : 0.01f*v3;
                    }
                    float2 f0 = __half22float2(*(const __half2*)(DmH + o0));
                    float2 f1 = __half22float2(*(const __half2*)(DmH + o1));
                    v0 += f0.x; v1 += f0.y; v2 += f1.x; v3 += f1.y;
                    *(float2*)(C + o0) = make_float2(v0, v1);
                    *(float2*)(C + o1) = make_float2(v2, v3);
                }
            }
        }
    }
}

template<int MODE>
__global__ __launch_bounds__(256, 2) void gemm_one(
    const __half* __restrict__ A, const __half* __restrict__ Bt,
    const float* __restrict__ bias, const __half* __restrict__ DmH,
    float* __restrict__ C, int N, int K)
{
    extern __shared__ char smem[];
    gemm_body<MODE>(A, Bt, bias, DmH, C, N, K, smem, 0, blockIdx.y);
}

__global__ __launch_bounds__(256, 2) void gemm_fold(
    const __half* __restrict__ Wqh, const __half* __restrict__ Wkh,
    const __half* __restrict__ Wvh, const __half* __restrict__ inwT,
    __half* __restrict__ WqT, __half* __restrict__ WkT, __half* __restrict__ WvT)
{
    extern __shared__ char smem[];
    int z = blockIdx.z;
    int M = (z == 0) ? DMODEL : LATD;
    if ((int)blockIdx.y*128 >= M) return;
    const __half* A = (z==0) ? Wqh : (z==1) ? Wkh : Wvh;
    const __half* Bt = inwT + (size_t)z*DMODEL*DMODEL;
    __half* C = (z==0) ? WqT : (z==1) ? WkT : WvT;
    gemm_body<4>(A, Bt, nullptr, nullptr, C, DMODEL, DMODEL, smem, M, blockIdx.y);
}

__global__ __launch_bounds__(256, 2) void gemm_all(
    const __half* __restrict__ dense_h, const __half* __restrict__ cond_h,
    const __half* __restrict__ WqT, const __half* __restrict__ WkT,
    const __half* __restrict__ WvT,
    const float* __restrict__ bq2, const float* __restrict__ bk2,
    const float* __restrict__ bv2,
    __half* __restrict__ qh2, __half* __restrict__ kh2, __half* __restrict__ vh2)
{
    extern __shared__ char smem[];
    int y = blockIdx.y;
    if (y < 124)
        gemm_body<3>(dense_h, WqT, bq2, nullptr, (void*)qh2, DMODEL, DMODEL, smem, 0, y);
    else if (y < 156)
        gemm_body<3>(cond_h, WkT, bk2, nullptr, (void*)kh2, DMODEL, LATD, smem, 0, y - 124);
    else
        gemm_body<3>(cond_h, WvT, bv2, nullptr, (void*)vh2, DMODEL, LATD, smem, 0, y - 156);
}

// ---------------- fp16 attention v4: 1024 threads, double-buffered K/V/Q ---
#define TB    64
#define QSTR  72
#define KVSTR 72
#define PSTR2 264
#define AK_BYTES (SEQ*KVSTR*2)     // 36864
#define AQ_BYTES (TB*QSTR*2)       // 9216
#define SM_K  0
#define SM_V  (2*AK_BYTES)         // 73728
#define SM_Q  (SM_V + 2*AK_BYTES)  // 147456
#define SM_P  (SM_Q + 2*AQ_BYTES)  // 165888
#define SM_MASK (SM_P + TB*PSTR2*2)// 199680
#define ATT_SMEM (SM_MASK + SEQ*4) // 200704

__global__ __launch_bounds__(1024, 1) void attn_f16(
    const __half* __restrict__ qh2, const __half* __restrict__ kh2,
    const __half* __restrict__ vh2, const int* __restrict__ maskp,
    __half* __restrict__ ctx, float* __restrict__ av_out)
{
    extern __shared__ char smc[];
    __half* sP  = (__half*)(smc + SM_P);
    int* sMask  = (int*)(smc + SM_MASK);

    int b = blockIdx.y, lt = blockIdx.x;
    int tid = threadIdx.x;
    int w = tid >> 5, lane = tid & 31;
    int p = lane >> 2, q = lane & 3;

    unsigned sk = (unsigned)__cvta_generic_to_shared(smc + SM_K);
    unsigned sv = (unsigned)__cvta_generic_to_shared(smc + SM_V);
    unsigned sq = (unsigned)__cvta_generic_to_shared(smc + SM_Q);
    unsigned spb = (unsigned)__cvta_generic_to_shared(sP);
    (void)spb;

    if (tid < SEQ) sMask[tid] = maskp[b*SEQ + tid];

    // QK^T roles: cw = 16-col tile (0..15), mh = m-half (0..1)
    int cw = w & 15, mh = w >> 4;
    unsigned aQ = sq + ((mh*32 + (lane & 15))*QSTR + (lane >> 4)*8)*2;
    unsigned bK = sk + ((cw*16 + ((lane >> 4) << 3) + (lane & 7))*KVSTR
                        + ((lane >> 3) & 1)*8)*2;
    // PV roles: m-tile mtw (0..3), d-group dg (0..7, 8 cols)
    int mtw = w & 3, dg = w >> 2;
    unsigned aP = (unsigned)__cvta_generic_to_shared(sP)
                  + ((mtw*16 + (lane & 15))*PSTR2 + (lane >> 4)*8)*2;
    unsigned bV = sv + (((lane & 7) + ((lane >> 3) & 1)*8)*KVSTR + dg*8)*2;

    // cp.async roles
    int qrow = tid >> 3, qch = tid & 7;     // valid for tid < 512
    int ql = lt*TB + (qrow & 63); if (ql > LMAX-1) ql = LMAX-1;

    // ---- prologue: head 0 into buf 0 ----
    {
        const __half* kg = kh2 + (size_t)b*SEQ*DMODEL;
        const __half* vg = vh2 + (size_t)b*SEQ*DMODEL;
        #pragma unroll
        for (int i = 0; i < 2; i++) {
            int c = tid + 1024*i;
            int s = c >> 3, ch = c & 7;
            CP16(sk + (s*KVSTR + ch*8)*2, kg + (size_t)s*DMODEL + ch*8);
            CP16(sv + (s*KVSTR + ch*8)*2, vg + (size_t)s*DMODEL + ch*8);
        }
        if (tid < 512)
            CP16(sq + (qrow*QSTR + qch*8)*2,
                 qh2 + (size_t)(b*LMAX + ql)*DMODEL + qch*8);
    }
    asm volatile("cp.async.commit_group;");

    float avacc[2][8];
    #pragma unroll
    for (int rr = 0; rr < 2; rr++)
        #pragma unroll
        for (int jj = 0; jj < 8; jj++) avacc[rr][jj] = 0.f;

    for (int h = 0; h < NH; h++) {
        int buf = h & 1;
        __syncthreads();
        if (h + 1 < NH) {
            int hh = h + 1, ob = buf ^ 1;
            const __half* kg = kh2 + (size_t)b*SEQ*DMODEL + hh*DH;
            const __half* vg = vh2 + (size_t)b*SEQ*DMODEL + hh*DH;
            #pragma unroll
            for (int i = 0; i < 2; i++) {
                int c = tid + 1024*i;
                int s = c >> 3, ch = c & 7;
                CP16(sk + ob*AK_BYTES + (s*KVSTR + ch*8)*2, kg + (size_t)s*DMODEL + ch*8);
                CP16(sv + ob*AK_BYTES + (s*KVSTR + ch*8)*2, vg + (size_t)s*DMODEL + ch*8);
            }
            if (tid < 512)
                CP16(sq + ob*AQ_BYTES + (qrow*QSTR + qch*8)*2,
                     qh2 + (size_t)(b*LMAX + ql)*DMODEL + hh*DH + qch*8);
        }
        asm volatile("cp.async.commit_group;");
        asm volatile("cp.async.wait_group 1;");
        __syncthreads();

        unsigned aQb = aQ + buf*AQ_BYTES;
        unsigned bKb = bK + buf*AK_BYTES;
        unsigned bVb = bV + buf*AK_BYTES;

        // ---- QK^T: warp (cw, mh): cols [16cw,16cw+16), m-tiles {2mh,2mh+1} ----
        float csc[2][2][4];
        #pragma unroll
        for (int j = 0; j < 2; j++)
            #pragma unroll
            for (int mt = 0; mt < 2; mt++)
                #pragma unroll
                for (int i = 0; i < 4; i++) csc[j][mt][i] = 0.f;
        #pragma unroll
        for (int ks = 0; ks < 4; ks++) {
            int kk = ks*16;
            unsigned bfr[4];
            LDSM4(bfr, bKb + kk*2);
            #pragma unroll
            for (int mt = 0; mt < 2; mt++) {
                unsigned afr[4];
                LDSM4(afr, aQb + (mt*16*QSTR + kk)*2);
                mma_f16(csc[0][mt], afr[0], afr[1], afr[2], afr[3], bfr[0], bfr[1]);
                mma_f16(csc[1][mt], afr[0], afr[1], afr[2], afr[3], bfr[2], bfr[3]);
            }
        }
        #pragma unroll
        for (int j = 0; j < 2; j++)
            #pragma unroll
            for (int mt = 0; mt < 2; mt++) {
                int row = (mh*2 + mt)*16 + p;
                int col = (2*cw + j)*8 + 2*q;
                *(__half2*)&sP[row*PSTR2 + col]     = __floats2half2_rn(csc[j][mt][0], csc[j][mt][1]);
                *(__half2*)&sP[(row+8)*PSTR2 + col] = __floats2half2_rn(csc[j][mt][2], csc[j][mt][3]);
            }
        __syncthreads();
        // ---- softmax: warp w owns rows [2w, 2w+2) ----
        #pragma unroll
        for (int rr = 0; rr < 2; rr++) {
            int row = 2*w + rr;
            float v[8];
            float m = -1e30f;
            #pragma unroll
            for (int jj = 0; jj < 8; jj++) {
                int s = lane + 32*jj;
                float x = sMask[s] ? -1e30f : __half2float(sP[row*PSTR2 + s])*0.125f;
                v[jj] = x;
                m = fmaxf(m, x);
            }
            #pragma unroll
            for (int o = 16; o > 0; o >>= 1) m = fmaxf(m, __shfl_xor_sync(0xffffffffu, m, o));
            float sum = 0.f;
            #pragma unroll
            for (int jj = 0; jj < 8; jj++) { v[jj] = __expf(v[jj] - m); sum += v[jj]; }
            #pragma unroll
            for (int o = 16; o > 0; o >>= 1) sum += __shfl_xor_sync(0xffffffffu, sum, o);
            float inv = 1.f/sum;
            #pragma unroll
            for (int jj = 0; jj < 8; jj++) {
                float pp = v[jj]*inv;
                avacc[rr][jj] += pp;
                sP[row*PSTR2 + lane + 32*jj] = __float2half_rn(pp);
            }
        }
        __syncthreads();
        // ---- P@V: warp (mtw, dg): m-tile mtw, d-cols [8dg, 8dg+8) ----
        float cct[4];
        #pragma unroll
        for (int i = 0; i < 4; i++) cct[i] = 0.f;
        #pragma unroll 4
        for (int ks = 0; ks < 16; ks++) {
            int kk = ks*16;
            unsigned afr[4], bfr[2];
            LDSM4(afr, aP + kk*2);
            LDSM2T(bfr, bVb + kk*KVSTR*2);
            mma_f16(cct, afr[0], afr[1], afr[2], afr[3], bfr[0], bfr[1]);
        }
        {
            int dc = h*DH + dg*8 + 2*q;
            int l0 = lt*TB + mtw*16 + p;
            if (l0 < LMAX)
                *(__half2*)&ctx[((size_t)(b*LMAX) + l0)*DMODEL + dc] =
                    __floats2half2_rn(cct[0], cct[1]);
            int l1 = l0 + 8;
            if (l1 < LMAX)
                *(__half2*)&ctx[((size_t)(b*LMAX) + l1)*DMODEL + dc] =
                    __floats2half2_rn(cct[2], cct[3]);
        }
    }

    // ---- head-averaged attention ----
    #pragma unroll
    for (int rr = 0; rr < 2; rr++) {
        int l = lt*TB + 2*w + rr;
        if (l < LMAX) {
            #pragma unroll
            for (int jj = 0; jj < 8; jj++)
                av_out[((size_t)(b*LMAX) + l)*SEQ + lane + 32*jj] = avacc[rr][jj]*0.125f;
        }
    }
}

// ---------------- LN1: half operand only ----------
__global__ __launch_bounds__(128) void ln_half(
    const float* __restrict__ x, const float* __restrict__ g,
    const float* __restrict__ bb, __half* __restrict__ yh)
{
    __shared__ float ws[4], wss[4];
    int r = blockIdx.x;
    int tid = threadIdx.x;
    const float4* xr = (const float4*)(x + (size_t)r*DMODEL);
    float4 v = xr[tid];
    float s  = v.x + v.y + v.z + v.w;
    float ss = v.x*v.x + v.y*v.y + v.z*v.z + v.w*v.w;
    #pragma unroll
    for (int o = 16; o > 0; o >>= 1) {
        s  += __shfl_xor_sync(0xffffffffu, s,  o);
        ss += __shfl_xor_sync(0xffffffffu, ss, o);
    }
    int warp = tid >> 5, lane = tid & 31;
    if (lane == 0) { ws[warp] = s; wss[warp] = ss; }
    __syncthreads();
    float S  = ws[0] + ws[1] + ws[2] + ws[3];
    float SS = wss[0] + wss[1] + wss[2] + wss[3];
    float mean = S * (1.f/DMODEL);
    float var  = SS * (1.f/DMODEL) - mean*mean;
    float rstd = rsqrtf(var + 1e-5f);
    float4 gg = ((const float4*)g)[tid];
    float4 b4 = ((const float4*)bb)[tid];
    float4 o4;
    o4.x = (v.x - mean)*rstd*gg.x + b4.x;
    o4.y = (v.y - mean)*rstd*gg.y + b4.y;
    o4.z = (v.z - mean)*rstd*gg.z + b4.z;
    o4.w = (v.w - mean)*rstd*gg.w + b4.w;
    __half2* yhp = (__half2*)(yh + (size_t)r*DMODEL);
    yhp[tid*2]   = __floats2half2_rn(o4.x, o4.y);
    yhp[tid*2+1] = __floats2half2_rn(o4.z, o4.w);
}

// ---------------- fused LN2 + ragged gather ----------
__global__ __launch_bounds__(128) void ln_gather(
    const float* __restrict__ x, const int* __restrict__ gb,
    const float* __restrict__ g, const float* __restrict__ bb,
    float* __restrict__ out)
{
    __shared__ float ws[4], wss[4];
    int i = blockIdx.x;
    int b = gb[i];
    int pp = i - lower_bound_gb(gb, b);
    size_t row = (size_t)b*LMAX + pp;
    int tid = threadIdx.x;
    float4 v = ((const float4*)(x + row*DMODEL))[tid];
    float s  = v.x + v.y + v.z + v.w;
    float ss = v.x*v.x + v.y*v.y + v.z*v.z + v.w*v.w;
    #pragma unroll
    for (int o = 16; o > 0; o >>= 1) {
        s  += __shfl_xor_sync(0xffffffffu, s,  o);
        ss += __shfl_xor_sync(0xffffffffu, ss, o);
    }
    int warp = tid >> 5, lane = tid & 31;
    if (lane == 0) { ws[warp] = s; wss[warp] = ss; }
    __syncthreads();
    float S  = ws[0] + ws[1] + ws[2] + ws[3];
    float SS = wss[0] + wss[1] + wss[2] + wss[3];
    float mean = S * (1.f/DMODEL);
    float var  = SS * (1.f/DMODEL) - mean*mean;
    float rstd = rsqrtf(var + 1e-5f);
    float4 gg = ((const float4*)g)[tid];
    float4 b4 = ((const float4*)bb)[tid];
    float4 o4;
    o4.x = (v.x - mean)*rstd*gg.x + b4.x;
    o4.y = (v.y - mean)*rstd*gg.y + b4.y;
    o4.z = (v.z - mean)*rstd*gg.z + b4.z;
    o4.w = (v.w - mean)*rstd*gg.w + b4.w;
    ((float4*)(out + (size_t)i*DMODEL))[tid] = o4;
}

// ---------------- launch ----------------
extern "C" void kernel_launch(void* const* d_in, const int* in_sizes, int n_in,
                              void* d_out, int out_size)
{
    int off = (n_in >= 22) ? 0 : 2;
    const float* nodes  = (const float*)d_in[0];
    const int*   gb     = (const int*)  d_in[1];
    const float* cond   = (const float*)d_in[2];
    const int*   maskp  = (const int*)  d_in[3];
    const float* Wq     = (const float*)d_in[6-off];
    const float* bq     = (const float*)d_in[7-off];
    const float* Wk     = (const float*)d_in[8-off];
    const float* bk     = (const float*)d_in[9-off];
    const float* Wv     = (const float*)d_in[10-off];
    const float* bv     = (const float*)d_in[11-off];
    const float* in_w   = (const float*)d_in[12-off];
    const float* in_b   = (const float*)d_in[13-off];
    const float* Wo     = (const float*)d_in[14-off];
    const float* bo     = (const float*)d_in[15-off];
    const float* ln1g   = (const float*)d_in[16-off];
    const float* ln1b   = (const float*)d_in[17-off];
    const float* W1     = (const float*)d_in[18-off];
    const float* b1     = (const float*)d_in[19-off];
    const float* ln2g   = (const float*)d_in[20-off];
    const float* ln2b   = (const float*)d_in[21-off];
    float* out = (float*)d_out;
    float* av_out = out + (size_t)NN*DMODEL;

    float *p_y, *p_h, *p_bq2, *p_bk2, *p_bv2;
    __half *p_dense_h, *p_qh2, *p_kh2, *p_vh2, *p_ctx, *p_x1h;
    __half *p_WqT, *p_WkT, *p_WvT, *p_WoT, *p_W1T, *p_cond;
    __half *p_Wqh, *p_Wkh, *p_Wvh, *p_inwT;
    cudaGetSymbolAddress((void**)&p_dense_h, g_dense_h);
    cudaGetSymbolAddress((void**)&p_qh2, g_qh2);
    cudaGetSymbolAddress((void**)&p_kh2, g_kh2);
    cudaGetSymbolAddress((void**)&p_vh2, g_vh2);
    cudaGetSymbolAddress((void**)&p_ctx, g_ctx);
    cudaGetSymbolAddress((void**)&p_y, g_y);
    cudaGetSymbolAddress((void**)&p_x1h, g_x1h);
    cudaGetSymbolAddress((void**)&p_h, g_h);
    cudaGetSymbolAddress((void**)&p_WqT, g_WqT);
    cudaGetSymbolAddress((void**)&p_WkT, g_WkT);
    cudaGetSymbolAddress((void**)&p_WvT, g_WvT);
    cudaGetSymbolAddress((void**)&p_WoT, g_WoT);
    cudaGetSymbolAddress((void**)&p_W1T, g_W1T);
    cudaGetSymbolAddress((void**)&p_cond, g_cond);
    cudaGetSymbolAddress((void**)&p_Wqh, g_Wqh);
    cudaGetSymbolAddress((void**)&p_Wkh, g_Wkh);
    cudaGetSymbolAddress((void**)&p_Wvh, g_Wvh);
    cudaGetSymbolAddress((void**)&p_inwT, g_inwT);
    cudaGetSymbolAddress((void**)&p_bq2, g_bq2);
    cudaGetSymbolAddress((void**)&p_bk2, g_bk2);
    cudaGetSymbolAddress((void**)&p_bv2, g_bv2);

    cudaFuncSetAttribute(gemm_one<1>, cudaFuncAttributeMaxDynamicSharedMemorySize, GEMM_SMEM);
    cudaFuncSetAttribute(gemm_one<2>, cudaFuncAttributeMaxDynamicSharedMemorySize, GEMM_SMEM);
    cudaFuncSetAttribute(gemm_all,    cudaFuncAttributeMaxDynamicSharedMemorySize, GEMM_SMEM);
    cudaFuncSetAttribute(gemm_fold,   cudaFuncAttributeMaxDynamicSharedMemorySize, GEMM_SMEM);
    cudaFuncSetAttribute(attn_f16,    cudaFuncAttributeMaxDynamicSharedMemorySize, ATT_SMEM);

    // 1) mega prologue
    prologue_misc<<<PM_TINW, 128>>>(nodes, gb, cond, Wo, W1, Wq, Wk, Wv,
                                    bq, bk, bv, in_w, in_b,
                                    p_dense_h, p_cond, p_WoT, p_W1T,
                                    p_Wqh, p_Wkh, p_Wvh, p_inwT,
                                    p_bq2, p_bk2, p_bv2);
    // 2) fold projection weights
    gemm_fold<<<dim3(4,6,3), 256, GEMM_SMEM>>>(p_Wqh, p_Wkh, p_Wvh, p_inwT,
                                               p_WqT, p_WkT, p_WvT);
    // 3) Q + K + V projections (flattened grid)
    gemm_all<<<dim3(4,188), 256, GEMM_SMEM>>>(p_dense_h, p_cond, p_WqT, p_WkT, p_WvT,
                                              p_bq2, p_bk2, p_bv2, p_qh2, p_kh2, p_vh2);
    // 4) fp16 attention v4 (1024 threads)  <-- profiled launch
    attn_f16<<<dim3(16, BGR), 1024, ATT_SMEM>>>(p_qh2, p_kh2, p_vh2, maskp, p_ctx, av_out);
    // 5) out proj + residual (half residual)
    gemm_one<1><<<dim3(4,124), 256, GEMM_SMEM>>>(p_ctx, p_WoT, bo, p_dense_h, p_y, DMODEL, DMODEL);
    // 6) LN1 -> half operand/residual
    ln_half<<<ROWS_Q, 128>>>(p_y, ln1g, ln1b, p_x1h);
    // 7) FFN + leaky + residual (half residual)
    gemm_one<2><<<dim3(4,124), 256, GEMM_SMEM>>>(p_x1h, p_W1T, b1, p_x1h, p_h, DMODEL, DMODEL);
    // 8) LN2 + ragged gather
    ln_gather<<<NN, 128>>>(p_h, gb, ln2g, ln2b, out);
}

// round 15
// speedup vs baseline: 1.0295x; 1.0295x over previous
#include <cuda_runtime.h>
#include <cuda_fp16.h>
#include <cuda_bf16.h>
#include <math.h>

// ---------------- problem constants ----------------
#define NN    12032
#define DMODEL 512
#define BGR   16
#define SEQ   256
#define NH    8
#define DH    64
#define LMAX  992
#define LATD  768
#define ROWS_Q  (BGR*LMAX)   // 15872
#define ROWS_KV (BGR*SEQ)    // 4096

// ---------------- scratch ----------
__device__ __half g_dense_h[ROWS_Q*DMODEL];
__device__ __half g_qh2 [ROWS_Q*DMODEL];
__device__ __half g_kh2 [ROWS_KV*DMODEL];
__device__ __half g_vh2 [ROWS_KV*DMODEL];
__device__ __half g_ctx [ROWS_Q*DMODEL];
__device__ float  g_y   [ROWS_Q*DMODEL];
__device__ __half g_x1h [ROWS_Q*DMODEL];
__device__ float  g_h   [ROWS_Q*DMODEL];
__device__ __half g_WqT [DMODEL*DMODEL];
__device__ __half g_WkT [LATD*DMODEL];
__device__ __half g_WvT [LATD*DMODEL];
__device__ __half g_WoT [DMODEL*DMODEL];
__device__ __half g_W1T [DMODEL*DMODEL];
__device__ __half g_cond[BGR*SEQ*LATD];
__device__ __half g_Wqh [DMODEL*DMODEL];
__device__ __half g_Wkh [LATD*DMODEL];
__device__ __half g_Wvh [LATD*DMODEL];
__device__ __half g_inwT[3*DMODEL*DMODEL];
__device__ float  g_bq2 [DMODEL];
__device__ float  g_bk2 [DMODEL];
__device__ float  g_bv2 [DMODEL];

// ---------------- helpers ----------------
__device__ __forceinline__ void mma_f16(float c[4],
    unsigned a0, unsigned a1, unsigned a2, unsigned a3,
    unsigned b0, unsigned b1)
{
    asm volatile(
        "mma.sync.aligned.m16n8k16.row.col.f32.f16.f16.f32 "
        "{%0,%1,%2,%3}, {%4,%5,%6,%7}, {%8,%9}, {%0,%1,%2,%3};"
        : "+f"(c[0]), "+f"(c[1]), "+f"(c[2]), "+f"(c[3])
        : "r"(a0), "r"(a1), "r"(a2), "r"(a3), "r"(b0), "r"(b1));
}

#define CP16(dst, src) asm volatile("cp.async.cg.shared.global [%0], [%1], 16;" :: "r"(dst), "l"(src))
#define LDSM4(r, addr) asm volatile( \
    "ldmatrix.sync.aligned.m8n8.x4.shared.b16 {%0,%1,%2,%3}, [%4];" \
    : "=r"((r)[0]), "=r"((r)[1]), "=r"((r)[2]), "=r"((r)[3]) : "r"(addr))
#define LDSM4T(r, addr) asm volatile( \
    "ldmatrix.sync.aligned.m8n8.x4.trans.shared.b16 {%0,%1,%2,%3}, [%4];" \
    : "=r"((r)[0]), "=r"((r)[1]), "=r"((r)[2]), "=r"((r)[3]) : "r"(addr))

__device__ __forceinline__ int lower_bound_gb(const int* __restrict__ gb, int b) {
    int lo = 0, hi = NN;
    while (lo < hi) { int mid = (lo + hi) >> 1; if (gb[mid] < b) lo = mid + 1; else hi = mid; }
    return lo;
}

// ---------------- mega-prologue ----------
#define PM_PAD   ROWS_Q             // 15872
#define PM_COND  (PM_PAD + 2048)    // 17920
#define PM_HT    (PM_COND + 512)    // 18432
#define PM_BIAS  (PM_HT + 48)       // 18480
#define PM_CONVW (PM_BIAS + 512)    // 18992
#define PM_TINW  (PM_CONVW + 768)   // 19760 (grid size)

__global__ __launch_bounds__(128) void prologue_misc(
    const float* __restrict__ nodes, const int* __restrict__ gb,
    const float* __restrict__ cond,  const float* __restrict__ Wo,
    const float* __restrict__ W1,
    const float* __restrict__ Wq, const float* __restrict__ Wk,
    const float* __restrict__ Wv,
    const float* __restrict__ bq, const float* __restrict__ bk,
    const float* __restrict__ bv, const float* __restrict__ inw,
    const float* __restrict__ inb,
    __half* __restrict__ dense_h,
    __half* __restrict__ cond_h, __half* __restrict__ WoT, __half* __restrict__ W1T,
    __half* __restrict__ Wqh, __half* __restrict__ Wkh, __half* __restrict__ Wvh,
    __half* __restrict__ inwT,
    float* __restrict__ bq2, float* __restrict__ bk2, float* __restrict__ bv2)
{
    __shared__ float sh[32*33];
    int bid = blockIdx.x, tid = threadIdx.x;
    if (bid < PM_PAD) {
        int r = bid;
        int b = r / LMAX, pp = r - b*LMAX;
        int start = lower_bound_gb(gb, b);
        int i = start + pp;
        float4 v = make_float4(0.f, 0.f, 0.f, 0.f);
        if (i < NN && gb[i] == b)
            v = ((const float4*)(nodes + (size_t)i*DMODEL))[tid];
        __half2* dh = (__half2*)(dense_h + (size_t)r*DMODEL);
        dh[tid*2]   = __floats2half2_rn(v.x, v.y);
        dh[tid*2+1] = __floats2half2_rn(v.z, v.w);
    } else if (bid < PM_COND) {
        int j = bid - PM_PAD;
        int n4 = (BGR*SEQ*LATD) >> 2;
        for (int i = j*128 + tid; i < n4; i += 2048*128) {
            float4 v = ((const float4*)cond)[i];
            __half2* d = (__half2*)cond_h;
            d[i*2]   = __floats2half2_rn(v.x, v.y);
            d[i*2+1] = __floats2half2_rn(v.z, v.w);
        }
    } else if (bid < PM_HT) {
        int t = bid - PM_COND;
        int z = t >> 8, rem = t & 255;
        const float* s = z ? W1 : Wo;
        __half* d = z ? W1T : WoT;
        int bx = (rem & 15)*32, by = (rem >> 4)*32;
        int x = tid & 31, y0 = tid >> 5;
        #pragma unroll
        for (int i = 0; i < 32; i += 4)
            sh[(y0+i)*33 + x] = s[(size_t)(by + y0 + i)*DMODEL + bx + x];
        __syncthreads();
        #pragma unroll
        for (int i = 0; i < 32; i += 4)
            d[(size_t)(bx + y0 + i)*DMODEL + by + x] = __float2half_rn(sh[x*33 + y0+i]);
    } else if (bid < PM_BIAS) {
        int t = bid - PM_HT;
        int z = t >> 4, blk = t & 15;
        const float* bin = (z==0) ? bq : (z==1) ? bk : bv;
        const float* W = inw + (size_t)z*DMODEL*DMODEL;
        const float* ab = inb + z*DMODEL;
        float* outp = (z==0) ? bq2 : (z==1) ? bk2 : bv2;
        int jj = tid & 31;
        int r = tid >> 5;
        int j = blk*32 + jj;
        float a = 0.f;
        #pragma unroll 8
        for (int i = r*128; i < r*128 + 128; i++)
            a += bin[i]*W[(size_t)i*DMODEL + j];
        sh[r*32 + jj] = a;
        __syncthreads();
        if (r == 0) {
            float s = ab[j];
            #pragma unroll
            for (int k = 0; k < 4; k++) s += sh[k*32 + jj];
            outp[j] = s;
        }
    } else if (bid < PM_CONVW) {
        int t = bid - PM_BIAS;
        #pragma unroll
        for (int i = 0; i < 4; i++) {
            int idx = t*512 + i*128 + tid;
            const float* src; __half* dst; int loc;
            if (idx < 65536)       { src = Wq; dst = Wqh; loc = idx; }
            else if (idx < 163840) { src = Wk; dst = Wkh; loc = idx - 65536; }
            else                   { src = Wv; dst = Wvh; loc = idx - 163840; }
            float4 v = ((const float4*)src)[loc];
            ((__half2*)dst)[loc*2]   = __floats2half2_rn(v.x, v.y);
            ((__half2*)dst)[loc*2+1] = __floats2half2_rn(v.z, v.w);
        }
    } else {
        int t = bid - PM_CONVW;
        int z = t >> 8, rem = t & 255;
        const float* s = inw + (size_t)z*DMODEL*DMODEL;
        __half* d = inwT + (size_t)z*DMODEL*DMODEL;
        int bx = (rem & 15)*32, by = (rem >> 4)*32;
        int x = tid & 31, y0 = tid >> 5;
        #pragma unroll
        for (int i = 0; i < 32; i += 4)
            sh[(y0+i)*33 + x] = s[(size_t)(by + y0 + i)*DMODEL + bx + x];
        __syncthreads();
        #pragma unroll
        for (int i = 0; i < 32; i += 4)
            d[(size_t)(bx + y0 + i)*DMODEL + by + x] = __float2half_rn(sh[x*33 + y0+i]);
    }
}

// ---------------- 3-stage cp.async FP16 GEMM ----------------
// MODE 1: C(fp32) = A@B + bias + DmH(half) ; MODE 2: leaky then += DmH
// MODE 3: C(half) = A@B + bias ; MODE 4: C(half, transposed CT[n*Mstr+m])
#define TSTRH 40
#define STG_B (128*TSTRH*2)
#define GEMM_SMEM (3*2*STG_B)

template<int MODE>
__device__ __forceinline__ void gemm_body(
    const __half* __restrict__ A, const __half* __restrict__ Bt,
    const float* __restrict__ bias, const __half* __restrict__ DmH,
    void* __restrict__ Cv, int N, int K, char* smem, int Mstr, int by)
{
    char* As = smem;
    char* Bs = smem + 3*STG_B;

    int tid = threadIdx.x;
    int warp = tid >> 5, lane = tid & 31;
    int warp_m = warp & 3, warp_n = warp >> 2;
    int p = lane >> 2, q = lane & 3;
    int blockM = by * 128;
    int blockN = blockIdx.x * 128;

    int c0 = tid*2, c1 = c0 + 1;
    int r0c = c0 >> 2, k0c = (c0 & 3)*8;
    int r1c = c1 >> 2, k1c = (c1 & 3)*8;

    const __half* gA0 = A  + (size_t)(blockM + r0c)*K + k0c;
    const __half* gA1 = A  + (size_t)(blockM + r1c)*K + k1c;
    const __half* gB0 = Bt + (size_t)(blockN + r0c)*K + k0c;
    const __half* gB1 = Bt + (size_t)(blockN + r1c)*K + k1c;

    unsigned sa = (unsigned)__cvta_generic_to_shared(As);
    unsigned sb = (unsigned)__cvta_generic_to_shared(Bs);
    unsigned dA0[3], dA1[3], dB0[3], dB1[3];
    #pragma unroll
    for (int s = 0; s < 3; s++) {
        dA0[s] = sa + s*STG_B + (r0c*TSTRH + k0c)*2;
        dA1[s] = sa + s*STG_B + (r1c*TSTRH + k1c)*2;
        dB0[s] = sb + s*STG_B + (r0c*TSTRH + k0c)*2;
        dB1[s] = sb + s*STG_B + (r1c*TSTRH + k1c)*2;
    }

    unsigned aBase = sa + ((warp_m*32 + (lane & 15))*TSTRH + (lane >> 4)*8)*2;
    unsigned bBase = sb + ((warp_n*64 + ((lane >> 4) << 3) + (lane & 7))*TSTRH
                           + ((lane >> 3) & 1)*8)*2;

    float acc[2][8][4];
    #pragma unroll
    for (int mt = 0; mt < 2; mt++)
        #pragma unroll
        for (int nt = 0; nt < 8; nt++)
            #pragma unroll
            for (int i = 0; i < 4; i++) acc[mt][nt][i] = 0.f;

    CP16(dA0[0], gA0); CP16(dA1[0], gA1);
    CP16(dB0[0], gB0); CP16(dB1[0], gB1);
    asm volatile("cp.async.commit_group;");
    CP16(dA0[1], gA0 + 32); CP16(dA1[1], gA1 + 32);
    CP16(dB0[1], gB0 + 32); CP16(dB1[1], gB1 + 32);
    asm volatile("cp.async.commit_group;");

    int nk = K >> 5;
    int sc = 0, sp = 2;
    for (int t = 0; t < nk; t++) {
        asm volatile("cp.async.wait_group 1;");
        __syncthreads();
        if (t + 2 < nk) {
            int kt = (t + 2) << 5;
            CP16(dA0[sp], gA0 + kt); CP16(dA1[sp], gA1 + kt);
            CP16(dB0[sp], gB0 + kt); CP16(dB1[sp], gB1 + kt);
        }
        asm volatile("cp.async.commit_group;");
        unsigned ao = aBase + sc*STG_B;
        unsigned bo = bBase + sc*STG_B;
        #pragma unroll
        for (int kk = 0; kk < 32; kk += 16) {
            unsigned afr[2][4];
            LDSM4(afr[0], ao + kk*2);
            LDSM4(afr[1], ao + (16*TSTRH + kk)*2);
            unsigned bfr[4][4];
            #pragma unroll
            for (int j = 0; j < 4; j++)
                LDSM4(bfr[j], bo + (j*16*TSTRH + kk)*2);
            #pragma unroll
            for (int mt = 0; mt < 2; mt++)
                #pragma unroll
                for (int nt = 0; nt < 8; nt++)
                    mma_f16(acc[mt][nt],
                            afr[mt][0], afr[mt][1], afr[mt][2], afr[mt][3],
                            bfr[nt >> 1][(nt & 1)*2], bfr[nt >> 1][(nt & 1)*2 + 1]);
        }
        sc++; if (sc == 3) sc = 0;
        sp++; if (sp == 3) sp = 0;
    }

    #pragma unroll
    for (int mt = 0; mt < 2; mt++) {
        int r0 = blockM + warp_m*32 + mt*16 + p;
        #pragma unroll
        for (int nt = 0; nt < 8; nt++) {
            int c0c = blockN + warp_n*64 + nt*8 + 2*q;
            float b0 = 0.f, b1 = 0.f;
            if (bias) { b0 = bias[c0c]; b1 = bias[c0c+1]; }
            float v0 = acc[mt][nt][0] + b0;
            float v1 = acc[mt][nt][1] + b1;
            float v2 = acc[mt][nt][2] + b0;
            float v3 = acc[mt][nt][3] + b1;
            if (MODE == 4) {
                __half* Ch = (__half*)Cv;
                Ch[(size_t)(c0c  )*Mstr + r0    ] = __float2half_rn(v0);
                Ch[(size_t)(c0c+1)*Mstr + r0    ] = __float2half_rn(v1);
                Ch[(size_t)(c0c  )*Mstr + r0 + 8] = __float2half_rn(v2);
                Ch[(size_t)(c0c+1)*Mstr + r0 + 8] = __float2half_rn(v3);
            } else {
                size_t o0 = (size_t)r0*N + c0c;
                size_t o1 = (size_t)(r0+8)*N + c0c;
                if (MODE == 3) {
                    __half* Ch = (__half*)Cv;
                    *(__half2*)&Ch[o0] = __floats2half2_rn(v0, v1);
                    *(__half2*)&Ch[o1] = __floats2half2_rn(v2, v3);
                } else {
                    float* C = (float*)Cv;
                    if (MODE == 2) {
                        v0 = (v0 > 0.f) ? v0 : 0.01f*v0;
                        v1 = (v1 > 0.f) ? v1 : 0.01f*v1;
                        v2 = (v2 > 0.f) ? v2 : 0.01f*v2;
                        v3 = (v3 > 0.f) ? v3 : 0.01f*v3;
                    }
                    float2 f0 = __half22float2(*(const __half2*)(DmH + o0));
                    float2 f1 = __half22float2(*(const __half2*)(DmH + o1));
                    v0 += f0.x; v1 += f0.y; v2 += f1.x; v3 += f1.y;
                    *(float2*)(C + o0) = make_float2(v0, v1);
                    *(float2*)(C + o1) = make_float2(v2, v3);
                }
            }
        }
    }
}

template<int MODE>
__global__ __launch_bounds__(256, 2) void gemm_one(
    const __half* __restrict__ A, const __half* __restrict__ Bt,
    const float* __restrict__ bias, const __half* __restrict__ DmH,
    float* __restrict__ C, int N, int K)
{
    extern __shared__ char smem[];
    gemm_body<MODE>(A, Bt, bias, DmH, C, N, K, smem, 0, blockIdx.y);
}

// weight fold: z=0 Wq (M=512), z=1 Wk (M=768), z=2 Wv (M=768); writes CT half
__global__ __launch_bounds__(256, 2) void gemm_fold(
    const __half* __restrict__ Wqh, const __half* __restrict__ Wkh,
    const __half* __restrict__ Wvh, const __half* __restrict__ inwT,
    __half* __restrict__ WqT, __half* __restrict__ WkT, __half* __restrict__ WvT)
{
    extern __shared__ char smem[];
    int z = blockIdx.z;
    int M = (z == 0) ? DMODEL : LATD;
    if ((int)blockIdx.y*128 >= M) return;
    const __half* A = (z==0) ? Wqh : (z==1) ? Wkh : Wvh;
    const __half* Bt = inwT + (size_t)z*DMODEL*DMODEL;
    __half* C = (z==0) ? WqT : (z==1) ? WkT : WvT;
    gemm_body<4>(A, Bt, nullptr, nullptr, C, DMODEL, DMODEL, smem, M, blockIdx.y);
}

// Q + K + V projections in one flattened launch: y 0..123 Q, 124..155 K, 156..187 V
__global__ __launch_bounds__(256, 2) void gemm_all(
    const __half* __restrict__ dense_h, const __half* __restrict__ cond_h,
    const __half* __restrict__ WqT, const __half* __restrict__ WkT,
    const __half* __restrict__ WvT,
    const float* __restrict__ bq2, const float* __restrict__ bk2,
    const float* __restrict__ bv2,
    __half* __restrict__ qh2, __half* __restrict__ kh2, __half* __restrict__ vh2)
{
    extern __shared__ char smem[];
    int y = blockIdx.y;
    if (y < 124)
        gemm_body<3>(dense_h, WqT, bq2, nullptr, (void*)qh2, DMODEL, DMODEL, smem, 0, y);
    else if (y < 156)
        gemm_body<3>(cond_h, WkT, bk2, nullptr, (void*)kh2, DMODEL, LATD, smem, 0, y - 124);
    else
        gemm_body<3>(cond_h, WvT, bv2, nullptr, (void*)vh2, DMODEL, LATD, smem, 0, y - 156);
}

// ---------------- fp16 attention v3: 512 threads, double-buffered K/V/Q ----
#define TB    64
#define QSTR  72
#define KVSTR 72
#define PSTR2 264
#define AK_BYTES (SEQ*KVSTR*2)     // 36864
#define AQ_BYTES (TB*QSTR*2)       // 9216
#define SM_K  0
#define SM_V  (2*AK_BYTES)         // 73728
#define SM_Q  (SM_V + 2*AK_BYTES)  // 147456
#define SM_P  (SM_Q + 2*AQ_BYTES)  // 165888
#define SM_MASK (SM_P + TB*PSTR2*2)// 199680
#define ATT_SMEM (SM_MASK + SEQ*4) // 200704

__global__ __launch_bounds__(512, 1) void attn_f16(
    const __half* __restrict__ qh2, const __half* __restrict__ kh2,
    const __half* __restrict__ vh2, const int* __restrict__ maskp,
    __half* __restrict__ ctx, float* __restrict__ av_out)
{
    extern __shared__ char smc[];
    __half* sP  = (__half*)(smc + SM_P);
    int* sMask  = (int*)(smc + SM_MASK);

    int b = blockIdx.y, lt = blockIdx.x;
    int tid = threadIdx.x;
    int w = tid >> 5, lane = tid & 31;
    int p = lane >> 2, q = lane & 3;

    unsigned sk = (unsigned)__cvta_generic_to_shared(smc + SM_K);
    unsigned sv = (unsigned)__cvta_generic_to_shared(smc + SM_V);
    unsigned sq = (unsigned)__cvta_generic_to_shared(smc + SM_Q);
    unsigned spb = (unsigned)__cvta_generic_to_shared(sP);

    if (tid < SEQ) sMask[tid] = maskp[b*SEQ + tid];

    // per-lane mma smem bases (add buf offsets at use)
    unsigned aQ = sq + ((lane & 15)*QSTR + (lane >> 4)*8)*2;
    unsigned bK = sk + ((w*16 + ((lane >> 4) << 3) + (lane & 7))*KVSTR
                        + ((lane >> 3) & 1)*8)*2;
    int mtw = w & 3, ng = w >> 2;
    unsigned aP = spb + ((mtw*16 + (lane & 15))*PSTR2 + (lane >> 4)*8)*2;
    unsigned bV = sv + (((lane & 7) + ((lane >> 3) & 1)*8)*KVSTR
                        + ng*16 + (lane >> 4)*8)*2;

    // Q row/chunk for this thread's cp.async
    int qrow = tid >> 3, qch = tid & 7;
    int ql = lt*TB + qrow; if (ql > LMAX-1) ql = LMAX-1;

    // ---- prologue: issue head 0 into buf 0 ----
    {
        const __half* kg = kh2 + (size_t)b*SEQ*DMODEL;
        const __half* vg = vh2 + (size_t)b*SEQ*DMODEL;
        #pragma unroll
        for (int i = 0; i < 4; i++) {
            int c = tid + 512*i;
            int s = c >> 3, ch = c & 7;
            CP16(sk + (s*KVSTR + ch*8)*2, kg + (size_t)s*DMODEL + ch*8);
            CP16(sv + (s*KVSTR + ch*8)*2, vg + (size_t)s*DMODEL + ch*8);
        }
        CP16(sq + (qrow*QSTR + qch*8)*2,
             qh2 + (size_t)(b*LMAX + ql)*DMODEL + qch*8);
    }
    asm volatile("cp.async.commit_group;");

    float avacc[4][8];
    #pragma unroll
    for (int rr = 0; rr < 4; rr++)
        #pragma unroll
        for (int jj = 0; jj < 8; jj++) avacc[rr][jj] = 0.f;

    for (int h = 0; h < NH; h++) {
        int buf = h & 1;
        __syncthreads();
        if (h + 1 < NH) {
            int hh = h + 1, ob = buf ^ 1;
            const __half* kg = kh2 + (size_t)b*SEQ*DMODEL + hh*DH;
            const __half* vg = vh2 + (size_t)b*SEQ*DMODEL + hh*DH;
            #pragma unroll
            for (int i = 0; i < 4; i++) {
                int c = tid + 512*i;
                int s = c >> 3, ch = c & 7;
                CP16(sk + ob*AK_BYTES + (s*KVSTR + ch*8)*2, kg + (size_t)s*DMODEL + ch*8);
                CP16(sv + ob*AK_BYTES + (s*KVSTR + ch*8)*2, vg + (size_t)s*DMODEL + ch*8);
            }
            CP16(sq + ob*AQ_BYTES + (qrow*QSTR + qch*8)*2,
                 qh2 + (size_t)(b*LMAX + ql)*DMODEL + hh*DH + qch*8);
        }
        asm volatile("cp.async.commit_group;");
        asm volatile("cp.async.wait_group 1;");
        __syncthreads();

        unsigned aQb = aQ + buf*AQ_BYTES;
        unsigned bKb = bK + buf*AK_BYTES;
        unsigned bVb = bV + buf*AK_BYTES;

        // ---- QK^T: warp w owns cols [16w,16w+16), 4 m-tiles ----
        float csc[2][4][4];
        #pragma unroll
        for (int j = 0; j < 2; j++)
            #pragma unroll
            for (int mt = 0; mt < 4; mt++)
                #pragma unroll
                for (int i = 0; i < 4; i++) csc[j][mt][i] = 0.f;
        #pragma unroll
        for (int ks = 0; ks < 4; ks++) {
            int kk = ks*16;
            unsigned bfr[4];
            LDSM4(bfr, bKb + kk*2);
            #pragma unroll
            for (int mt = 0; mt < 4; mt++) {
                unsigned afr[4];
                LDSM4(afr, aQb + (mt*16*QSTR + kk)*2);
                mma_f16(csc[0][mt], afr[0], afr[1], afr[2], afr[3], bfr[0], bfr[1]);
                mma_f16(csc[1][mt], afr[0], afr[1], afr[2], afr[3], bfr[2], bfr[3]);
            }
        }
        // write raw scores to sP
        #pragma unroll
        for (int j = 0; j < 2; j++)
            #pragma unroll
            for (int mt = 0; mt < 4; mt++) {
                int row = mt*16 + p;
                int col = (2*w + j)*8 + 2*q;
                *(__half2*)&sP[row*PSTR2 + col]     = __floats2half2_rn(csc[j][mt][0], csc[j][mt][1]);
                *(__half2*)&sP[(row+8)*PSTR2 + col] = __floats2half2_rn(csc[j][mt][2], csc[j][mt][3]);
            }
        __syncthreads();
        // ---- softmax: warp w owns rows [4w,4w+4) ----
        #pragma unroll
        for (int rr = 0; rr < 4; rr++) {
            int row = 4*w + rr;
            float v[8];
            float m = -1e30f;
            #pragma unroll
            for (int jj = 0; jj < 8; jj++) {
                int s = lane + 32*jj;
                float x = sMask[s] ? -1e30f : __half2float(sP[row*PSTR2 + s])*0.125f;
                v[jj] = x;
                m = fmaxf(m, x);
            }
            #pragma unroll
            for (int o = 16; o > 0; o >>= 1) m = fmaxf(m, __shfl_xor_sync(0xffffffffu, m, o));
            float sum = 0.f;
            #pragma unroll
            for (int jj = 0; jj < 8; jj++) { v[jj] = __expf(v[jj] - m); sum += v[jj]; }
            #pragma unroll
            for (int o = 16; o > 0; o >>= 1) sum += __shfl_xor_sync(0xffffffffu, sum, o);
            float inv = 1.f/sum;
            #pragma unroll
            for (int jj = 0; jj < 8; jj++) {
                float pp = v[jj]*inv;
                avacc[rr][jj] += pp;
                sP[row*PSTR2 + lane + 32*jj] = __float2half_rn(pp);
            }
        }
        __syncthreads();
        // ---- P@V: warp w -> m-tile mtw, d-cols [16ng, 16ng+16) ----
        float cct[2][4];
        #pragma unroll
        for (int j = 0; j < 2; j++)
            #pragma unroll
            for (int i = 0; i < 4; i++) cct[j][i] = 0.f;
        #pragma unroll 4
        for (int ks = 0; ks < 16; ks++) {
            int kk = ks*16;
            unsigned afr[4], bfr[4];
            LDSM4(afr, aP + kk*2);
            LDSM4T(bfr, bVb + kk*KVSTR*2);
            mma_f16(cct[0], afr[0], afr[1], afr[2], afr[3], bfr[0], bfr[1]);
            mma_f16(cct[1], afr[0], afr[1], afr[2], afr[3], bfr[2], bfr[3]);
        }
        #pragma unroll
        for (int j = 0; j < 2; j++) {
            int dc = h*DH + ng*16 + j*8 + 2*q;
            int l0 = lt*TB + mtw*16 + p;
            if (l0 < LMAX)
                *(__half2*)&ctx[((size_t)(b*LMAX) + l0)*DMODEL + dc] =
                    __floats2half2_rn(cct[j][0], cct[j][1]);
            int l1 = l0 + 8;
            if (l1 < LMAX)
                *(__half2*)&ctx[((size_t)(b*LMAX) + l1)*DMODEL + dc] =
                    __floats2half2_rn(cct[j][2], cct[j][3]);
        }
    }

    // ---- head-averaged attention ----
    #pragma unroll
    for (int rr = 0; rr < 4; rr++) {
        int l = lt*TB + 4*w + rr;
        if (l < LMAX) {
            #pragma unroll
            for (int jj = 0; jj < 8; jj++)
                av_out[((size_t)(b*LMAX) + l)*SEQ + lane + 32*jj] = avacc[rr][jj]*0.125f;
        }
    }
}

// ---------------- LN1: half operand only ----------
__global__ __launch_bounds__(128) void ln_half(
    const float* __restrict__ x, const float* __restrict__ g,
    const float* __restrict__ bb, __half* __restrict__ yh)
{
    __shared__ float ws[4], wss[4];
    int r = blockIdx.x;
    int tid = threadIdx.x;
    const float4* xr = (const float4*)(x + (size_t)r*DMODEL);
    float4 v = xr[tid];
    float s  = v.x + v.y + v.z + v.w;
    float ss = v.x*v.x + v.y*v.y + v.z*v.z + v.w*v.w;
    #pragma unroll
    for (int o = 16; o > 0; o >>= 1) {
        s  += __shfl_xor_sync(0xffffffffu, s,  o);
        ss += __shfl_xor_sync(0xffffffffu, ss, o);
    }
    int warp = tid >> 5, lane = tid & 31;
    if (lane == 0) { ws[warp] = s; wss[warp] = ss; }
    __syncthreads();
    float S  = ws[0] + ws[1] + ws[2] + ws[3];
    float SS = wss[0] + wss[1] + wss[2] + wss[3];
    float mean = S * (1.f/DMODEL);
    float var  = SS * (1.f/DMODEL) - mean*mean;
    float rstd = rsqrtf(var + 1e-5f);
    float4 gg = ((const float4*)g)[tid];
    float4 b4 = ((const float4*)bb)[tid];
    float4 o4;
    o4.x = (v.x - mean)*rstd*gg.x + b4.x;
    o4.y = (v.y - mean)*rstd*gg.y + b4.y;
    o4.z = (v.z - mean)*rstd*gg.z + b4.z;
    o4.w = (v.w - mean)*rstd*gg.w + b4.w;
    __half2* yhp = (__half2*)(yh + (size_t)r*DMODEL);
    yhp[tid*2]   = __floats2half2_rn(o4.x, o4.y);
    yhp[tid*2+1] = __floats2half2_rn(o4.z, o4.w);
}

// ---------------- fused LN2 + ragged gather ----------
__global__ __launch_bounds__(128) void ln_gather(
    const float* __restrict__ x, const int* __restrict__ gb,
    const float* __restrict__ g, const float* __restrict__ bb,
    float* __restrict__ out)
{
    __shared__ float ws[4], wss[4];
    int i = blockIdx.x;
    int b = gb[i];
    int pp = i - lower_bound_gb(gb, b);
    size_t row = (size_t)b*LMAX + pp;
    int tid = threadIdx.x;
    float4 v = ((const float4*)(x + row*DMODEL))[tid];
    float s  = v.x + v.y + v.z + v.w;
    float ss = v.x*v.x + v.y*v.y + v.z*v.z + v.w*v.w;
    #pragma unroll
    for (int o = 16; o > 0; o >>= 1) {
        s  += __shfl_xor_sync(0xffffffffu, s,  o);
        ss += __shfl_xor_sync(0xffffffffu, ss, o);
    }
    int warp = tid >> 5, lane = tid & 31;
    if (lane == 0) { ws[warp] = s; wss[warp] = ss; }
    __syncthreads();
    float S  = ws[0] + ws[1] + ws[2] + ws[3];
    float SS = wss[0] + wss[1] + wss[2] + wss[3];
    float mean = S * (1.f/DMODEL);
    float var  = SS * (1.f/DMODEL) - mean*mean;
    float rstd = rsqrtf(var + 1e-5f);
    float4 gg = ((const float4*)g)[tid];
    float4 b4 = ((const float4*)bb)[tid];
    float4 o4;
    o4.x = (v.x - mean)*rstd*gg.x + b4.x;
    o4.y = (v.y - mean)*rstd*gg.y + b4.y;
    o4.z = (v.z - mean)*rstd*gg.z + b4.z;
    o4.w = (v.w - mean)*rstd*gg.w + b4.w;
    ((float4*)(out + (size_t)i*DMODEL))[tid] = o4;
}

// ---------------- launch ----------------
extern "C" void kernel_launch(void* const* d_in, const int* in_sizes, int n_in,
                              void* d_out, int out_size)
{
    int off = (n_in >= 22) ? 0 : 2;
    const float* nodes  = (const float*)d_in[0];
    const int*   gb     = (const int*)  d_in[1];
    const float* cond   = (const float*)d_in[2];
    const int*   maskp  = (const int*)  d_in[3];
    const float* Wq     = (const float*)d_in[6-off];
    const float* bq     = (const float*)d_in[7-off];
    const float* Wk     = (const float*)d_in[8-off];
    const float* bk     = (const float*)d_in[9-off];
    const float* Wv     = (const float*)d_in[10-off];
    const float* bv     = (const float*)d_in[11-off];
    const float* in_w   = (const float*)d_in[12-off];
    const float* in_b   = (const float*)d_in[13-off];
    const float* Wo     = (const float*)d_in[14-off];
    const float* bo     = (const float*)d_in[15-off];
    const float* ln1g   = (const float*)d_in[16-off];
    const float* ln1b   = (const float*)d_in[17-off];
    const float* W1     = (const float*)d_in[18-off];
    const float* b1     = (const float*)d_in[19-off];
    const float* ln2g   = (const float*)d_in[20-off];
    const float* ln2b   = (const float*)d_in[21-off];
    float* out = (float*)d_out;
    float* av_out = out + (size_t)NN*DMODEL;

    float *p_y, *p_h, *p_bq2, *p_bk2, *p_bv2;
    __half *p_dense_h, *p_qh2, *p_kh2, *p_vh2, *p_ctx, *p_x1h;
    __half *p_WqT, *p_WkT, *p_WvT, *p_WoT, *p_W1T, *p_cond;
    __half *p_Wqh, *p_Wkh, *p_Wvh, *p_inwT;
    cudaGetSymbolAddress((void**)&p_dense_h, g_dense_h);
    cudaGetSymbolAddress((void**)&p_qh2, g_qh2);
    cudaGetSymbolAddress((void**)&p_kh2, g_kh2);
    cudaGetSymbolAddress((void**)&p_vh2, g_vh2);
    cudaGetSymbolAddress((void**)&p_ctx, g_ctx);
    cudaGetSymbolAddress((void**)&p_y, g_y);
    cudaGetSymbolAddress((void**)&p_x1h, g_x1h);
    cudaGetSymbolAddress((void**)&p_h, g_h);
    cudaGetSymbolAddress((void**)&p_WqT, g_WqT);
    cudaGetSymbolAddress((void**)&p_WkT, g_WkT);
    cudaGetSymbolAddress((void**)&p_WvT, g_WvT);
    cudaGetSymbolAddress((void**)&p_WoT, g_WoT);
    cudaGetSymbolAddress((void**)&p_W1T, g_W1T);
    cudaGetSymbolAddress((void**)&p_cond, g_cond);
    cudaGetSymbolAddress((void**)&p_Wqh, g_Wqh);
    cudaGetSymbolAddress((void**)&p_Wkh, g_Wkh);
    cudaGetSymbolAddress((void**)&p_Wvh, g_Wvh);
    cudaGetSymbolAddress((void**)&p_inwT, g_inwT);
    cudaGetSymbolAddress((void**)&p_bq2, g_bq2);
    cudaGetSymbolAddress((void**)&p_bk2, g_bk2);
    cudaGetSymbolAddress((void**)&p_bv2, g_bv2);

    cudaFuncSetAttribute(gemm_one<1>, cudaFuncAttributeMaxDynamicSharedMemorySize, GEMM_SMEM);
    cudaFuncSetAttribute(gemm_one<2>, cudaFuncAttributeMaxDynamicSharedMemorySize, GEMM_SMEM);
    cudaFuncSetAttribute(gemm_all,    cudaFuncAttributeMaxDynamicSharedMemorySize, GEMM_SMEM);
    cudaFuncSetAttribute(gemm_fold,   cudaFuncAttributeMaxDynamicSharedMemorySize, GEMM_SMEM);
    cudaFuncSetAttribute(attn_f16,    cudaFuncAttributeMaxDynamicSharedMemorySize, ATT_SMEM);

    // 1) mega prologue
    prologue_misc<<<PM_TINW, 128>>>(nodes, gb, cond, Wo, W1, Wq, Wk, Wv,
                                    bq, bk, bv, in_w, in_b,
                                    p_dense_h, p_cond, p_WoT, p_W1T,
                                    p_Wqh, p_Wkh, p_Wvh, p_inwT,
                                    p_bq2, p_bk2, p_bv2);
    // 2) fold projection weights
    gemm_fold<<<dim3(4,6,3), 256, GEMM_SMEM>>>(p_Wqh, p_Wkh, p_Wvh, p_inwT,
                                               p_WqT, p_WkT, p_WvT);
    // 3) Q + K + V projections (flattened grid)
    gemm_all<<<dim3(4,188), 256, GEMM_SMEM>>>(p_dense_h, p_cond, p_WqT, p_WkT, p_WvT,
                                              p_bq2, p_bk2, p_bv2, p_qh2, p_kh2, p_vh2);
    // 4) fp16 attention v3 (512 threads)
    attn_f16<<<dim3(16, BGR), 512, ATT_SMEM>>>(p_qh2, p_kh2, p_vh2, maskp, p_ctx, av_out);
    // 5) out proj + residual (half residual)
    gemm_one<1><<<dim3(4,124), 256, GEMM_SMEM>>>(p_ctx, p_WoT, bo, p_dense_h, p_y, DMODEL, DMODEL);
    // 6) LN1 -> half operand/residual
    ln_half<<<ROWS_Q, 128>>>(p_y, ln1g, ln1b, p_x1h);
    // 7) FFN + leaky + residual (half residual)
    gemm_one<2><<<dim3(4,124), 256, GEMM_SMEM>>>(p_x1h, p_W1T, b1, p_x1h, p_h, DMODEL, DMODEL);
    // 8) LN2 + ragged gather
    ln_gather<<<NN, 128>>>(p_h, gb, ln2g, ln2b, out);
}

// round 16
// speedup vs baseline: 1.0621x; 1.0316x over previous
#include <cuda_runtime.h>
#include <cuda_fp16.h>
#include <cuda_bf16.h>
#include <math.h>

// ---------------- problem constants ----------------
#define NN    12032
#define DMODEL 512
#define BGR   16
#define SEQ   256
#define NH    8
#define DH    64
#define LMAX  992
#define LATD  768
#define ROWS_Q  (BGR*LMAX)   // 15872
#define ROWS_KV (BGR*SEQ)    // 4096

// ---------------- scratch ----------
__device__ __half g_dense_h[ROWS_Q*DMODEL];
__device__ __half g_qh2 [ROWS_Q*DMODEL];
__device__ __half g_kh2 [ROWS_KV*DMODEL];
__device__ __half g_vh2 [ROWS_KV*DMODEL];
__device__ __half g_ctx [ROWS_Q*DMODEL];
__device__ float  g_y   [ROWS_Q*DMODEL];
__device__ __half g_x1h [ROWS_Q*DMODEL];
__device__ float  g_h   [ROWS_Q*DMODEL];
__device__ __half g_WqT [DMODEL*DMODEL];
__device__ __half g_WkT [LATD*DMODEL];
__device__ __half g_WvT [LATD*DMODEL];
__device__ __half g_WoT [DMODEL*DMODEL];
__device__ __half g_W1T [DMODEL*DMODEL];
__device__ __half g_cond[BGR*SEQ*LATD];
__device__ __half g_Wqh [DMODEL*DMODEL];
__device__ __half g_Wkh [LATD*DMODEL];
__device__ __half g_Wvh [LATD*DMODEL];
__device__ __half g_inwT[3*DMODEL*DMODEL];
__device__ float  g_bq2 [DMODEL];
__device__ float  g_bk2 [DMODEL];
__device__ float  g_bv2 [DMODEL];

// ---------------- helpers ----------------
__device__ __forceinline__ void mma_f16(float c[4],
    unsigned a0, unsigned a1, unsigned a2, unsigned a3,
    unsigned b0, unsigned b1)
{
    asm volatile(
        "mma.sync.aligned.m16n8k16.row.col.f32.f16.f16.f32 "
        "{%0,%1,%2,%3}, {%4,%5,%6,%7}, {%8,%9}, {%0,%1,%2,%3};"
        : "+f"(c[0]), "+f"(c[1]), "+f"(c[2]), "+f"(c[3])
        : "r"(a0), "r"(a1), "r"(a2), "r"(a3), "r"(b0), "r"(b1));
}

#define CP16(dst, src) asm volatile("cp.async.cg.shared.global [%0], [%1], 16;" :: "r"(dst), "l"(src))
#define LDSM4(r, addr) asm volatile( \
    "ldmatrix.sync.aligned.m8n8.x4.shared.b16 {%0,%1,%2,%3}, [%4];" \
    : "=r"((r)[0]), "=r"((r)[1]), "=r"((r)[2]), "=r"((r)[3]) : "r"(addr))
#define LDSM4T(r, addr) asm volatile( \
    "ldmatrix.sync.aligned.m8n8.x4.trans.shared.b16 {%0,%1,%2,%3}, [%4];" \
    : "=r"((r)[0]), "=r"((r)[1]), "=r"((r)[2]), "=r"((r)[3]) : "r"(addr))

__device__ __forceinline__ int lower_bound_gb(const int* __restrict__ gb, int b) {
    int lo = 0, hi = NN;
    while (lo < hi) { int mid = (lo + hi) >> 1; if (gb[mid] < b) lo = mid + 1; else hi = mid; }
    return lo;
}

// ---------------- mega-prologue ----------
#define PM_PAD   ROWS_Q             // 15872
#define PM_COND  (PM_PAD + 2048)    // 17920
#define PM_HT    (PM_COND + 512)    // 18432
#define PM_BIAS  (PM_HT + 48)       // 18480
#define PM_CONVW (PM_BIAS + 512)    // 18992
#define PM_TINW  (PM_CONVW + 768)   // 19760 (grid size)

__global__ __launch_bounds__(128) void prologue_misc(
    const float* __restrict__ nodes, const int* __restrict__ gb,
    const float* __restrict__ cond,  const float* __restrict__ Wo,
    const float* __restrict__ W1,
    const float* __restrict__ Wq, const float* __restrict__ Wk,
    const float* __restrict__ Wv,
    const float* __restrict__ bq, const float* __restrict__ bk,
    const float* __restrict__ bv, const float* __restrict__ inw,
    const float* __restrict__ inb,
    __half* __restrict__ dense_h,
    __half* __restrict__ cond_h, __half* __restrict__ WoT, __half* __restrict__ W1T,
    __half* __restrict__ Wqh, __half* __restrict__ Wkh, __half* __restrict__ Wvh,
    __half* __restrict__ inwT,
    float* __restrict__ bq2, float* __restrict__ bk2, float* __restrict__ bv2)
{
    __shared__ float sh[32*33];
    int bid = blockIdx.x, tid = threadIdx.x;
    if (bid < PM_PAD) {
        int r = bid;
        int b = r / LMAX, pp = r - b*LMAX;
        int start = lower_bound_gb(gb, b);
        int i = start + pp;
        float4 v = make_float4(0.f, 0.f, 0.f, 0.f);
        if (i < NN && gb[i] == b)
            v = ((const float4*)(nodes + (size_t)i*DMODEL))[tid];
        __half2* dh = (__half2*)(dense_h + (size_t)r*DMODEL);
        dh[tid*2]   = __floats2half2_rn(v.x, v.y);
        dh[tid*2+1] = __floats2half2_rn(v.z, v.w);
    } else if (bid < PM_COND) {
        int j = bid - PM_PAD;
        int n4 = (BGR*SEQ*LATD) >> 2;
        for (int i = j*128 + tid; i < n4; i += 2048*128) {
            float4 v = ((const float4*)cond)[i];
            __half2* d = (__half2*)cond_h;
            d[i*2]   = __floats2half2_rn(v.x, v.y);
            d[i*2+1] = __floats2half2_rn(v.z, v.w);
        }
    } else if (bid < PM_HT) {
        int t = bid - PM_COND;
        int z = t >> 8, rem = t & 255;
        const float* s = z ? W1 : Wo;
        __half* d = z ? W1T : WoT;
        int bx = (rem & 15)*32, by = (rem >> 4)*32;
        int x = tid & 31, y0 = tid >> 5;
        #pragma unroll
        for (int i = 0; i < 32; i += 4)
            sh[(y0+i)*33 + x] = s[(size_t)(by + y0 + i)*DMODEL + bx + x];
        __syncthreads();
        #pragma unroll
        for (int i = 0; i < 32; i += 4)
            d[(size_t)(bx + y0 + i)*DMODEL + by + x] = __float2half_rn(sh[x*33 + y0+i]);
    } else if (bid < PM_BIAS) {
        int t = bid - PM_HT;
        int z = t >> 4, blk = t & 15;
        const float* bin = (z==0) ? bq : (z==1) ? bk : bv;
        const float* W = inw + (size_t)z*DMODEL*DMODEL;
        const float* ab = inb + z*DMODEL;
        float* outp = (z==0) ? bq2 : (z==1) ? bk2 : bv2;
        int jj = tid & 31;
        int r = tid >> 5;
        int j = blk*32 + jj;
        float a = 0.f;
        #pragma unroll 8
        for (int i = r*128; i < r*128 + 128; i++)
            a += bin[i]*W[(size_t)i*DMODEL + j];
        sh[r*32 + jj] = a;
        __syncthreads();
        if (r == 0) {
            float s = ab[j];
            #pragma unroll
            for (int k = 0; k < 4; k++) s += sh[k*32 + jj];
            outp[j] = s;
        }
    } else if (bid < PM_CONVW) {
        int t = bid - PM_BIAS;
        #pragma unroll
        for (int i = 0; i < 4; i++) {
            int idx = t*512 + i*128 + tid;
            const float* src; __half* dst; int loc;
            if (idx < 65536)       { src = Wq; dst = Wqh; loc = idx; }
            else if (idx < 163840) { src = Wk; dst = Wkh; loc = idx - 65536; }
            else                   { src = Wv; dst = Wvh; loc = idx - 163840; }
            float4 v = ((const float4*)src)[loc];
            ((__half2*)dst)[loc*2]   = __floats2half2_rn(v.x, v.y);
            ((__half2*)dst)[loc*2+1] = __floats2half2_rn(v.z, v.w);
        }
    } else {
        int t = bid - PM_CONVW;
        int z = t >> 8, rem = t & 255;
        const float* s = inw + (size_t)z*DMODEL*DMODEL;
        __half* d = inwT + (size_t)z*DMODEL*DMODEL;
        int bx = (rem & 15)*32, by = (rem >> 4)*32;
        int x = tid & 31, y0 = tid >> 5;
        #pragma unroll
        for (int i = 0; i < 32; i += 4)
            sh[(y0+i)*33 + x] = s[(size_t)(by + y0 + i)*DMODEL + bx + x];
        __syncthreads();
        #pragma unroll
        for (int i = 0; i < 32; i += 4)
            d[(size_t)(bx + y0 + i)*DMODEL + by + x] = __float2half_rn(sh[x*33 + y0+i]);
    }
}

// ---------------- 3-stage cp.async FP16 GEMM ----------------
// MODE 1: C(fp32) = A@B + bias + DmH(half) ; MODE 2: leaky then += DmH
// MODE 3: C(half) = A@B + bias ; MODE 4: C(half, transposed CT[n*Mstr+m])
#define TSTRH 40
#define STG_B (128*TSTRH*2)
#define GEMM_SMEM (3*2*STG_B)

template<int MODE>
__device__ __forceinline__ void gemm_body(
    const __half* __restrict__ A, const __half* __restrict__ Bt,
    const float* __restrict__ bias, const __half* __restrict__ DmH,
    void* __restrict__ Cv, int N, int K, char* smem, int Mstr, int by)
{
    char* As = smem;
    char* Bs = smem + 3*STG_B;

    int tid = threadIdx.x;
    int warp = tid >> 5, lane = tid & 31;
    int warp_m = warp & 3, warp_n = warp >> 2;
    int p = lane >> 2, q = lane & 3;
    int blockM = by * 128;
    int blockN = blockIdx.x * 128;

    int c0 = tid*2, c1 = c0 + 1;
    int r0c = c0 >> 2, k0c = (c0 & 3)*8;
    int r1c = c1 >> 2, k1c = (c1 & 3)*8;

    const __half* gA0 = A  + (size_t)(blockM + r0c)*K + k0c;
    const __half* gA1 = A  + (size_t)(blockM + r1c)*K + k1c;
    const __half* gB0 = Bt + (size_t)(blockN + r0c)*K + k0c;
    const __half* gB1 = Bt + (size_t)(blockN + r1c)*K + k1c;

    unsigned sa = (unsigned)__cvta_generic_to_shared(As);
    unsigned sb = (unsigned)__cvta_generic_to_shared(Bs);
    unsigned dA0[3], dA1[3], dB0[3], dB1[3];
    #pragma unroll
    for (int s = 0; s < 3; s++) {
        dA0[s] = sa + s*STG_B + (r0c*TSTRH + k0c)*2;
        dA1[s] = sa + s*STG_B + (r1c*TSTRH + k1c)*2;
        dB0[s] = sb + s*STG_B + (r0c*TSTRH + k0c)*2;
        dB1[s] = sb + s*STG_B + (r1c*TSTRH + k1c)*2;
    }

    unsigned aBase = sa + ((warp_m*32 + (lane & 15))*TSTRH + (lane >> 4)*8)*2;
    unsigned bBase = sb + ((warp_n*64 + ((lane >> 4) << 3) + (lane & 7))*TSTRH
                           + ((lane >> 3) & 1)*8)*2;

    float acc[2][8][4];
    #pragma unroll
    for (int mt = 0; mt < 2; mt++)
        #pragma unroll
        for (int nt = 0; nt < 8; nt++)
            #pragma unroll
            for (int i = 0; i < 4; i++) acc[mt][nt][i] = 0.f;

    CP16(dA0[0], gA0); CP16(dA1[0], gA1);
    CP16(dB0[0], gB0); CP16(dB1[0], gB1);
    asm volatile("cp.async.commit_group;");
    CP16(dA0[1], gA0 + 32); CP16(dA1[1], gA1 + 32);
    CP16(dB0[1], gB0 + 32); CP16(dB1[1], gB1 + 32);
    asm volatile("cp.async.commit_group;");

    int nk = K >> 5;
    int sc = 0, sp = 2;
    for (int t = 0; t < nk; t++) {
        asm volatile("cp.async.wait_group 1;");
        __syncthreads();
        if (t + 2 < nk) {
            int kt = (t + 2) << 5;
            CP16(dA0[sp], gA0 + kt); CP16(dA1[sp], gA1 + kt);
            CP16(dB0[sp], gB0 + kt); CP16(dB1[sp], gB1 + kt);
        }
        asm volatile("cp.async.commit_group;");
        unsigned ao = aBase + sc*STG_B;
        unsigned bo = bBase + sc*STG_B;
        #pragma unroll
        for (int kk = 0; kk < 32; kk += 16) {
            unsigned afr[2][4];
            LDSM4(afr[0], ao + kk*2);
            LDSM4(afr[1], ao + (16*TSTRH + kk)*2);
            unsigned bfr[4][4];
            #pragma unroll
            for (int j = 0; j < 4; j++)
                LDSM4(bfr[j], bo + (j*16*TSTRH + kk)*2);
            #pragma unroll
            for (int mt = 0; mt < 2; mt++)
                #pragma unroll
                for (int nt = 0; nt < 8; nt++)
                    mma_f16(acc[mt][nt],
                            afr[mt][0], afr[mt][1], afr[mt][2], afr[mt][3],
                            bfr[nt >> 1][(nt & 1)*2], bfr[nt >> 1][(nt & 1)*2 + 1]);
        }
        sc++; if (sc == 3) sc = 0;
        sp++; if (sp == 3) sp = 0;
    }

    #pragma unroll
    for (int mt = 0; mt < 2; mt++) {
        int r0 = blockM + warp_m*32 + mt*16 + p;
        #pragma unroll
        for (int nt = 0; nt < 8; nt++) {
            int c0c = blockN + warp_n*64 + nt*8 + 2*q;
            float b0 = 0.f, b1 = 0.f;
            if (bias) { b0 = bias[c0c]; b1 = bias[c0c+1]; }
            float v0 = acc[mt][nt][0] + b0;
            float v1 = acc[mt][nt][1] + b1;
            float v2 = acc[mt][nt][2] + b0;
            float v3 = acc[mt][nt][3] + b1;
            if (MODE == 4) {
                __half* Ch = (__half*)Cv;
                Ch[(size_t)(c0c  )*Mstr + r0    ] = __float2half_rn(v0);
                Ch[(size_t)(c0c+1)*Mstr + r0    ] = __float2half_rn(v1);
                Ch[(size_t)(c0c  )*Mstr + r0 + 8] = __float2half_rn(v2);
                Ch[(size_t)(c0c+1)*Mstr + r0 + 8] = __float2half_rn(v3);
            } else {
                size_t o0 = (size_t)r0*N + c0c;
                size_t o1 = (size_t)(r0+8)*N + c0c;
                if (MODE == 3) {
                    __half* Ch = (__half*)Cv;
                    *(__half2*)&Ch[o0] = __floats2half2_rn(v0, v1);
                    *(__half2*)&Ch[o1] = __floats2half2_rn(v2, v3);
                } else {
                    float* C = (float*)Cv;
                    if (MODE == 2) {
                        v0 = (v0 > 0.f) ? v0 : 0.01f*v0;
                        v1 = (v1 > 0.f) ? v1 : 0.01f*v1;
                        v2 = (v2 > 0.f) ? v2 : 0.01f*v2;
                        v3 = (v3 > 0.f) ? v3 : 0.01f*v3;
                    }
                    float2 f0 = __half22float2(*(const __half2*)(DmH + o0));
                    float2 f1 = __half22float2(*(const __half2*)(DmH + o1));
                    v0 += f0.x; v1 += f0.y; v2 += f1.x; v3 += f1.y;
                    *(float2*)(C + o0) = make_float2(v0, v1);
                    *(float2*)(C + o1) = make_float2(v2, v3);
                }
            }
        }
    }
}

template<int MODE>
__global__ __launch_bounds__(256, 2) void gemm_one(
    const __half* __restrict__ A, const __half* __restrict__ Bt,
    const float* __restrict__ bias, const __half* __restrict__ DmH,
    float* __restrict__ C, int N, int K)
{
    extern __shared__ char smem[];
    gemm_body<MODE>(A, Bt, bias, DmH, C, N, K, smem, 0, blockIdx.y);
}

// weight fold: z=0 Wq (M=512), z=1 Wk (M=768), z=2 Wv (M=768); writes CT half
__global__ __launch_bounds__(256, 2) void gemm_fold(
    const __half* __restrict__ Wqh, const __half* __restrict__ Wkh,
    const __half* __restrict__ Wvh, const __half* __restrict__ inwT,
    __half* __restrict__ WqT, __half* __restrict__ WkT, __half* __restrict__ WvT)
{
    extern __shared__ char smem[];
    int z = blockIdx.z;
    int M = (z == 0) ? DMODEL : LATD;
    if ((int)blockIdx.y*128 >= M) return;
    const __half* A = (z==0) ? Wqh : (z==1) ? Wkh : Wvh;
    const __half* Bt = inwT + (size_t)z*DMODEL*DMODEL;
    __half* C = (z==0) ? WqT : (z==1) ? WkT : WvT;
    gemm_body<4>(A, Bt, nullptr, nullptr, C, DMODEL, DMODEL, smem, M, blockIdx.y);
}

// Q + K + V projections in one flattened launch: y 0..123 Q, 124..155 K, 156..187 V
__global__ __launch_bounds__(256, 2) void gemm_all(
    const __half* __restrict__ dense_h, const __half* __restrict__ cond_h,
    const __half* __restrict__ WqT, const __half* __restrict__ WkT,
    const __half* __restrict__ WvT,
    const float* __restrict__ bq2, const float* __restrict__ bk2,
    const float* __restrict__ bv2,
    __half* __restrict__ qh2, __half* __restrict__ kh2, __half* __restrict__ vh2)
{
    extern __shared__ char smem[];
    int y = blockIdx.y;
    if (y < 124)
        gemm_body<3>(dense_h, WqT, bq2, nullptr, (void*)qh2, DMODEL, DMODEL, smem, 0, y);
    else if (y < 156)
        gemm_body<3>(cond_h, WkT, bk2, nullptr, (void*)kh2, DMODEL, LATD, smem, 0, y - 124);
    else
        gemm_body<3>(cond_h, WvT, bv2, nullptr, (void*)vh2, DMODEL, LATD, smem, 0, y - 156);
}

// ---------------- fp16 attention v5: fused no-max softmax ----------
#define TB    64
#define QSTR  72
#define KVSTR 72
#define PSTR2 264
#define AK_BYTES (SEQ*KVSTR*2)     // 36864
#define AQ_BYTES (TB*QSTR*2)       // 9216
#define SM_K  0
#define SM_V  (2*AK_BYTES)         // 73728
#define SM_Q  (SM_V + 2*AK_BYTES)  // 147456
#define SM_P  (SM_Q + 2*AQ_BYTES)  // 165888
#define SM_MASK (SM_P + TB*PSTR2*2)// 199680
#define SM_SUM (SM_MASK + SEQ*4)   // 200704 : float[64][17]
#define SM_INV (SM_SUM + 64*17*4)  // 205056 : float[64]
#define ATT_SMEM (SM_INV + 64*4)   // 205312

__global__ __launch_bounds__(512, 1) void attn_f16(
    const __half* __restrict__ qh2, const __half* __restrict__ kh2,
    const __half* __restrict__ vh2, const int* __restrict__ maskp,
    __half* __restrict__ ctx, float* __restrict__ av_out)
{
    extern __shared__ char smc[];
    __half* sP  = (__half*)(smc + SM_P);
    int* sMask  = (int*)(smc + SM_MASK);
    float* sSum = (float*)(smc + SM_SUM);
    float* sInv = (float*)(smc + SM_INV);

    int b = blockIdx.y, lt = blockIdx.x;
    int tid = threadIdx.x;
    int w = tid >> 5, lane = tid & 31;
    int p = lane >> 2, q = lane & 3;

    unsigned sk = (unsigned)__cvta_generic_to_shared(smc + SM_K);
    unsigned sv = (unsigned)__cvta_generic_to_shared(smc + SM_V);
    unsigned sq = (unsigned)__cvta_generic_to_shared(smc + SM_Q);
    unsigned spb = (unsigned)__cvta_generic_to_shared(sP);

    if (tid < SEQ) sMask[tid] = maskp[b*SEQ + tid];

    // per-lane mma smem bases (add buf offsets at use)
    unsigned aQ = sq + ((lane & 15)*QSTR + (lane >> 4)*8)*2;
    unsigned bK = sk + ((w*16 + ((lane >> 4) << 3) + (lane & 7))*KVSTR
                        + ((lane >> 3) & 1)*8)*2;
    int mtw = w & 3, ng = w >> 2;
    unsigned aP = spb + ((mtw*16 + (lane & 15))*PSTR2 + (lane >> 4)*8)*2;
    unsigned bV = sv + (((lane & 7) + ((lane >> 3) & 1)*8)*KVSTR
                        + ng*16 + (lane >> 4)*8)*2;

    // Q row/chunk for this thread's cp.async
    int qrow = tid >> 3, qch = tid & 7;
    int ql = lt*TB + qrow; if (ql > LMAX-1) ql = LMAX-1;

    // ---- prologue: issue head 0 into buf 0 ----
    {
        const __half* kg = kh2 + (size_t)b*SEQ*DMODEL;
        const __half* vg = vh2 + (size_t)b*SEQ*DMODEL;
        #pragma unroll
        for (int i = 0; i < 4; i++) {
            int c = tid + 512*i;
            int s = c >> 3, ch = c & 7;
            CP16(sk + (s*KVSTR + ch*8)*2, kg + (size_t)s*DMODEL + ch*8);
            CP16(sv + (s*KVSTR + ch*8)*2, vg + (size_t)s*DMODEL + ch*8);
        }
        CP16(sq + (qrow*QSTR + qch*8)*2,
             qh2 + (size_t)(b*LMAX + ql)*DMODEL + qch*8);
    }
    asm volatile("cp.async.commit_group;");

    // hoist per-fragment column masks (fixed across heads)
    __syncthreads();
    int mk[2][2];
    #pragma unroll
    for (int j = 0; j < 2; j++) {
        int c = (2*w + j)*8 + 2*q;
        mk[j][0] = sMask[c];
        mk[j][1] = sMask[c + 1];
    }

    float avacc[2][4][4];
    #pragma unroll
    for (int j = 0; j < 2; j++)
        #pragma unroll
        for (int mt = 0; mt < 4; mt++)
            #pragma unroll
            for (int i = 0; i < 4; i++) avacc[j][mt][i] = 0.f;

    for (int h = 0; h < NH; h++) {
        int buf = h & 1;
        __syncthreads();
        if (h + 1 < NH) {
            int hh = h + 1, ob = buf ^ 1;
            const __half* kg = kh2 + (size_t)b*SEQ*DMODEL + hh*DH;
            const __half* vg = vh2 + (size_t)b*SEQ*DMODEL + hh*DH;
            #pragma unroll
            for (int i = 0; i < 4; i++) {
                int c = tid + 512*i;
                int s = c >> 3, ch = c & 7;
                CP16(sk + ob*AK_BYTES + (s*KVSTR + ch*8)*2, kg + (size_t)s*DMODEL + ch*8);
                CP16(sv + ob*AK_BYTES + (s*KVSTR + ch*8)*2, vg + (size_t)s*DMODEL + ch*8);
            }
            CP16(sq + ob*AQ_BYTES + (qrow*QSTR + qch*8)*2,
                 qh2 + (size_t)(b*LMAX + ql)*DMODEL + hh*DH + qch*8);
        }
        asm volatile("cp.async.commit_group;");
        asm volatile("cp.async.wait_group 1;");
        __syncthreads();

        unsigned aQb = aQ + buf*AQ_BYTES;
        unsigned bKb = bK + buf*AK_BYTES;
        unsigned bVb = bV + buf*AK_BYTES;

        // ---- QK^T: warp w owns cols [16w,16w+16), 4 m-tiles ----
        float csc[2][4][4];
        #pragma unroll
        for (int j = 0; j < 2; j++)
            #pragma unroll
            for (int mt = 0; mt < 4; mt++)
                #pragma unroll
                for (int i = 0; i < 4; i++) csc[j][mt][i] = 0.f;
        #pragma unroll
        for (int ks = 0; ks < 4; ks++) {
            int kk = ks*16;
            unsigned bfr[4];
            LDSM4(bfr, bKb + kk*2);
            #pragma unroll
            for (int mt = 0; mt < 4; mt++) {
                unsigned afr[4];
                LDSM4(afr, aQb + (mt*16*QSTR + kk)*2);
                mma_f16(csc[0][mt], afr[0], afr[1], afr[2], afr[3], bfr[0], bfr[1]);
                mma_f16(csc[1][mt], afr[0], afr[1], afr[2], afr[3], bfr[2], bfr[3]);
            }
        }
        // ---- fused no-max softmax: exp + write + per-row partial sums ----
        float rs_lo[4], rs_hi[4];
        #pragma unroll
        for (int mt = 0; mt < 4; mt++) { rs_lo[mt] = 0.f; rs_hi[mt] = 0.f; }
        #pragma unroll
        for (int j = 0; j < 2; j++)
            #pragma unroll
            for (int mt = 0; mt < 4; mt++) {
                float e0 = mk[j][0] ? 0.f : __expf(csc[j][mt][0]*0.125f);
                float e1 = mk[j][1] ? 0.f : __expf(csc[j][mt][1]*0.125f);
                float e2 = mk[j][0] ? 0.f : __expf(csc[j][mt][2]*0.125f);
                float e3 = mk[j][1] ? 0.f : __expf(csc[j][mt][3]*0.125f);
                csc[j][mt][0] = e0; csc[j][mt][1] = e1;
                csc[j][mt][2] = e2; csc[j][mt][3] = e3;
                int row = mt*16 + p;
                int col = (2*w + j)*8 + 2*q;
                *(__half2*)&sP[row*PSTR2 + col]     = __floats2half2_rn(e0, e1);
                *(__half2*)&sP[(row+8)*PSTR2 + col] = __floats2half2_rn(e2, e3);
                rs_lo[mt] += e0 + e1;
                rs_hi[mt] += e2 + e3;
            }
        #pragma unroll
        for (int mt = 0; mt < 4; mt++) {
            rs_lo[mt] += __shfl_xor_sync(0xffffffffu, rs_lo[mt], 1);
            rs_lo[mt] += __shfl_xor_sync(0xffffffffu, rs_lo[mt], 2);
            rs_hi[mt] += __shfl_xor_sync(0xffffffffu, rs_hi[mt], 1);
            rs_hi[mt] += __shfl_xor_sync(0xffffffffu, rs_hi[mt], 2);
        }
        if (q == 0) {
            #pragma unroll
            for (int mt = 0; mt < 4; mt++) {
                sSum[(mt*16 + p)*17 + w]     = rs_lo[mt];
                sSum[(mt*16 + p + 8)*17 + w] = rs_hi[mt];
            }
        }
        __syncthreads();
        if (tid < 64) {
            float s = 0.f;
            #pragma unroll
            for (int k = 0; k < 16; k++) s += sSum[tid*17 + k];
            sInv[tid] = 1.f/s;
        }
        __syncthreads();
        // ---- av accumulation from retained exp fragments ----
        #pragma unroll
        for (int mt = 0; mt < 4; mt++) {
            float i0 = sInv[mt*16 + p];
            float i1 = sInv[mt*16 + p + 8];
            #pragma unroll
            for (int j = 0; j < 2; j++) {
                avacc[j][mt][0] += csc[j][mt][0]*i0;
                avacc[j][mt][1] += csc[j][mt][1]*i0;
                avacc[j][mt][2] += csc[j][mt][2]*i1;
                avacc[j][mt][3] += csc[j][mt][3]*i1;
            }
        }
        // ---- P@V (unnormalized), scale by invsum at epilogue ----
        float cct[2][4];
        #pragma unroll
        for (int j = 0; j < 2; j++)
            #pragma unroll
            for (int i = 0; i < 4; i++) cct[j][i] = 0.f;
        #pragma unroll 4
        for (int ks = 0; ks < 16; ks++) {
            int kk = ks*16;
            unsigned afr[4], bfr[4];
            LDSM4(afr, aP + kk*2);
            LDSM4T(bfr, bVb + kk*KVSTR*2);
            mma_f16(cct[0], afr[0], afr[1], afr[2], afr[3], bfr[0], bfr[1]);
            mma_f16(cct[1], afr[0], afr[1], afr[2], afr[3], bfr[2], bfr[3]);
        }
        {
            float iv0 = sInv[mtw*16 + p];
            float iv1 = sInv[mtw*16 + p + 8];
            #pragma unroll
            for (int j = 0; j < 2; j++) {
                int dc = h*DH + ng*16 + j*8 + 2*q;
                int l0 = lt*TB + mtw*16 + p;
                if (l0 < LMAX)
                    *(__half2*)&ctx[((size_t)(b*LMAX) + l0)*DMODEL + dc] =
                        __floats2half2_rn(cct[j][0]*iv0, cct[j][1]*iv0);
                int l1 = l0 + 8;
                if (l1 < LMAX)
                    *(__half2*)&ctx[((size_t)(b*LMAX) + l1)*DMODEL + dc] =
                        __floats2half2_rn(cct[j][2]*iv1, cct[j][3]*iv1);
            }
        }
    }

    // ---- head-averaged attention (fragment ownership) ----
    #pragma unroll
    for (int j = 0; j < 2; j++)
        #pragma unroll
        for (int mt = 0; mt < 4; mt++) {
            int col = (2*w + j)*8 + 2*q;
            int l0 = lt*TB + mt*16 + p;
            if (l0 < LMAX)
                *(float2*)&av_out[((size_t)(b*LMAX) + l0)*SEQ + col] =
                    make_float2(avacc[j][mt][0]*0.125f, avacc[j][mt][1]*0.125f);
            int l1 = l0 + 8;
            if (l1 < LMAX)
                *(float2*)&av_out[((size_t)(b*LMAX) + l1)*SEQ + col] =
                    make_float2(avacc[j][mt][2]*0.125f, avacc[j][mt][3]*0.125f);
        }
}

// ---------------- LN1: half operand only ----------
__global__ __launch_bounds__(128) void ln_half(
    const float* __restrict__ x, const float* __restrict__ g,
    const float* __restrict__ bb, __half* __restrict__ yh)
{
    __shared__ float ws[4], wss[4];
    int r = blockIdx.x;
    int tid = threadIdx.x;
    const float4* xr = (const float4*)(x + (size_t)r*DMODEL);
    float4 v = xr[tid];
    float s  = v.x + v.y + v.z + v.w;
    float ss = v.x*v.x + v.y*v.y + v.z*v.z + v.w*v.w;
    #pragma unroll
    for (int o = 16; o > 0; o >>= 1) {
        s  += __shfl_xor_sync(0xffffffffu, s,  o);
        ss += __shfl_xor_sync(0xffffffffu, ss, o);
    }
    int warp = tid >> 5, lane = tid & 31;
    if (lane == 0) { ws[warp] = s; wss[warp] = ss; }
    __syncthreads();
    float S  = ws[0] + ws[1] + ws[2] + ws[3];
    float SS = wss[0] + wss[1] + wss[2] + wss[3];
    float mean = S * (1.f/DMODEL);
    float var  = SS * (1.f/DMODEL) - mean*mean;
    float rstd = rsqrtf(var + 1e-5f);
    float4 gg = ((const float4*)g)[tid];
    float4 b4 = ((const float4*)bb)[tid];
    float4 o4;
    o4.x = (v.x - mean)*rstd*gg.x + b4.x;
    o4.y = (v.y - mean)*rstd*gg.y + b4.y;
    o4.z = (v.z - mean)*rstd*gg.z + b4.z;
    o4.w = (v.w - mean)*rstd*gg.w + b4.w;
    __half2* yhp = (__half2*)(yh + (size_t)r*DMODEL);
    yhp[tid*2]   = __floats2half2_rn(o4.x, o4.y);
    yhp[tid*2+1] = __floats2half2_rn(o4.z, o4.w);
}

// ---------------- fused LN2 + ragged gather ----------
__global__ __launch_bounds__(128) void ln_gather(
    const float* __restrict__ x, const int* __restrict__ gb,
    const float* __restrict__ g, const float* __restrict__ bb,
    float* __restrict__ out)
{
    __shared__ float ws[4], wss[4];
    int i = blockIdx.x;
    int b = gb[i];
    int pp = i - lower_bound_gb(gb, b);
    size_t row = (size_t)b*LMAX + pp;
    int tid = threadIdx.x;
    float4 v = ((const float4*)(x + row*DMODEL))[tid];
    float s  = v.x + v.y + v.z + v.w;
    float ss = v.x*v.x + v.y*v.y + v.z*v.z + v.w*v.w;
    #pragma unroll
    for (int o = 16; o > 0; o >>= 1) {
        s  += __shfl_xor_sync(0xffffffffu, s,  o);
        ss += __shfl_xor_sync(0xffffffffu, ss, o);
    }
    int warp = tid >> 5, lane = tid & 31;
    if (lane == 0) { ws[warp] = s; wss[warp] = ss; }
    __syncthreads();
    float S  = ws[0] + ws[1] + ws[2] + ws[3];
    float SS = wss[0] + wss[1] + wss[2] + wss[3];
    float mean = S * (1.f/DMODEL);
    float var  = SS * (1.f/DMODEL) - mean*mean;
    float rstd = rsqrtf(var + 1e-5f);
    float4 gg = ((const float4*)g)[tid];
    float4 b4 = ((const float4*)bb)[tid];
    float4 o4;
    o4.x = (v.x - mean)*rstd*gg.x + b4.x;
    o4.y = (v.y - mean)*rstd*gg.y + b4.y;
    o4.z = (v.z - mean)*rstd*gg.z + b4.z;
    o4.w = (v.w - mean)*rstd*gg.w + b4.w;
    ((float4*)(out + (size_t)i*DMODEL))[tid] = o4;
}

// ---------------- launch ----------------
extern "C" void kernel_launch(void* const* d_in, const int* in_sizes, int n_in,
                              void* d_out, int out_size)
{
    int off = (n_in >= 22) ? 0 : 2;
    const float* nodes  = (const float*)d_in[0];
    const int*   gb     = (const int*)  d_in[1];
    const float* cond   = (const float*)d_in[2];
    const int*   maskp  = (const int*)  d_in[3];
    const float* Wq     = (const float*)d_in[6-off];
    const float* bq     = (const float*)d_in[7-off];
    const float* Wk     = (const float*)d_in[8-off];
    const float* bk     = (const float*)d_in[9-off];
    const float* Wv     = (const float*)d_in[10-off];
    const float* bv     = (const float*)d_in[11-off];
    const float* in_w   = (const float*)d_in[12-off];
    const float* in_b   = (const float*)d_in[13-off];
    const float* Wo     = (const float*)d_in[14-off];
    const float* bo     = (const float*)d_in[15-off];
    const float* ln1g   = (const float*)d_in[16-off];
    const float* ln1b   = (const float*)d_in[17-off];
    const float* W1     = (const float*)d_in[18-off];
    const float* b1     = (const float*)d_in[19-off];
    const float* ln2g   = (const float*)d_in[20-off];
    const float* ln2b   = (const float*)d_in[21-off];
    float* out = (float*)d_out;
    float* av_out = out + (size_t)NN*DMODEL;

    float *p_y, *p_h, *p_bq2, *p_bk2, *p_bv2;
    __half *p_dense_h, *p_qh2, *p_kh2, *p_vh2, *p_ctx, *p_x1h;
    __half *p_WqT, *p_WkT, *p_WvT, *p_WoT, *p_W1T, *p_cond;
    __half *p_Wqh, *p_Wkh, *p_Wvh, *p_inwT;
    cudaGetSymbolAddress((void**)&p_dense_h, g_dense_h);
    cudaGetSymbolAddress((void**)&p_qh2, g_qh2);
    cudaGetSymbolAddress((void**)&p_kh2, g_kh2);
    cudaGetSymbolAddress((void**)&p_vh2, g_vh2);
    cudaGetSymbolAddress((void**)&p_ctx, g_ctx);
    cudaGetSymbolAddress((void**)&p_y, g_y);
    cudaGetSymbolAddress((void**)&p_x1h, g_x1h);
    cudaGetSymbolAddress((void**)&p_h, g_h);
    cudaGetSymbolAddress((void**)&p_WqT, g_WqT);
    cudaGetSymbolAddress((void**)&p_WkT, g_WkT);
    cudaGetSymbolAddress((void**)&p_WvT, g_WvT);
    cudaGetSymbolAddress((void**)&p_WoT, g_WoT);
    cudaGetSymbolAddress((void**)&p_W1T, g_W1T);
    cudaGetSymbolAddress((void**)&p_cond, g_cond);
    cudaGetSymbolAddress((void**)&p_Wqh, g_Wqh);
    cudaGetSymbolAddress((void**)&p_Wkh, g_Wkh);
    cudaGetSymbolAddress((void**)&p_Wvh, g_Wvh);
    cudaGetSymbolAddress((void**)&p_inwT, g_inwT);
    cudaGetSymbolAddress((void**)&p_bq2, g_bq2);
    cudaGetSymbolAddress((void**)&p_bk2, g_bk2);
    cudaGetSymbolAddress((void**)&p_bv2, g_bv2);

    cudaFuncSetAttribute(gemm_one<1>, cudaFuncAttributeMaxDynamicSharedMemorySize, GEMM_SMEM);
    cudaFuncSetAttribute(gemm_one<2>, cudaFuncAttributeMaxDynamicSharedMemorySize, GEMM_SMEM);
    cudaFuncSetAttribute(gemm_all,    cudaFuncAttributeMaxDynamicSharedMemorySize, GEMM_SMEM);
    cudaFuncSetAttribute(gemm_fold,   cudaFuncAttributeMaxDynamicSharedMemorySize, GEMM_SMEM);
    cudaFuncSetAttribute(attn_f16,    cudaFuncAttributeMaxDynamicSharedMemorySize, ATT_SMEM);

    // 1) mega prologue
    prologue_misc<<<PM_TINW, 128>>>(nodes, gb, cond, Wo, W1, Wq, Wk, Wv,
                                    bq, bk, bv, in_w, in_b,
                                    p_dense_h, p_cond, p_WoT, p_W1T,
                                    p_Wqh, p_Wkh, p_Wvh, p_inwT,
                                    p_bq2, p_bk2, p_bv2);
    // 2) fold projection weights
    gemm_fold<<<dim3(4,6,3), 256, GEMM_SMEM>>>(p_Wqh, p_Wkh, p_Wvh, p_inwT,
                                               p_WqT, p_WkT, p_WvT);
    // 3) Q + K + V projections (flattened grid)
    gemm_all<<<dim3(4,188), 256, GEMM_SMEM>>>(p_dense_h, p_cond, p_WqT, p_WkT, p_WvT,
                                              p_bq2, p_bk2, p_bv2, p_qh2, p_kh2, p_vh2);
    // 4) fp16 attention v5 (fused no-max softmax)  <-- profiled launch
    attn_f16<<<dim3(16, BGR), 512, ATT_SMEM>>>(p_qh2, p_kh2, p_vh2, maskp, p_ctx, av_out);
    // 5) out proj + residual (half residual)
    gemm_one<1><<<dim3(4,124), 256, GEMM_SMEM>>>(p_ctx, p_WoT, bo, p_dense_h, p_y, DMODEL, DMODEL);
    // 6) LN1 -> half operand/residual
    ln_half<<<ROWS_Q, 128>>>(p_y, ln1g, ln1b, p_x1h);
    // 7) FFN + leaky + residual (half residual)
    gemm_one<2><<<dim3(4,124), 256, GEMM_SMEM>>>(p_x1h, p_W1T, b1, p_x1h, p_h, DMODEL, DMODEL);
    // 8) LN2 + ragged gather
    ln_gather<<<NN, 128>>>(p_h, gb, ln2g, ln2b, out);
}